// round 1
// baseline (speedup 1.0000x reference)
#include <cuda_runtime.h>
#include <cuda_bf16.h>
#include <math.h>

// ---------------- problem constants ----------------
constexpr int Bg   = 256;     // graphs
constexpr int NPG  = 400;     // nodes per graph
constexpr int Ntot = Bg * NPG;        // 102400
constexpr int EPG  = 8000;    // edges per graph
constexpr int Etot = Bg * EPG;        // 2048000
constexpr int CIN  = 400;
constexpr int H    = 64;
constexpr int H3   = 128;
constexpr int KEEP = 200;
#define BN_RS 0.99999500003749968f  /* rsqrt(1+1e-5) */

// ---------------- scratch (device globals; no allocation allowed) ----------------
__device__ float g_xw1[Ntot * H];
__device__ float g_h1 [Ntot * H];
__device__ float g_xw2[Ntot * H];
__device__ float g_h2 [Ntot * H];
__device__ float g_xw3[Ntot * H3];
__device__ float g_h3 [Ntot * H3];
__device__ float g_dis [Ntot];
__device__ float g_dis3[Ntot];
__device__ float g_score[Ntot];
__device__ float g_mask[Ntot];
__device__ float g_gate[Ntot];
__device__ float g_emb[Bg * 4 * H];   // [B, 256]

// ---------------- degree / dis kernels ----------------
__global__ void k_fill(float* p, float v) {
    int i = blockIdx.x * 256 + threadIdx.x;
    p[i] = v;
}
__global__ void k_copy(float* dstp, const float* srcp) {
    int i = blockIdx.x * 256 + threadIdx.x;
    dstp[i] = srcp[i];
}
__global__ void k_accum_deg(const int* __restrict__ dst, const float* __restrict__ w,
                            float* __restrict__ deg) {
    int e = blockIdx.x * 256 + threadIdx.x;
    atomicAdd(&deg[dst[e]], w[e]);
}
__global__ void k_accum_deg3(const int* __restrict__ src, const int* __restrict__ dst,
                             const float* __restrict__ w, const float* __restrict__ mask,
                             float* __restrict__ deg) {
    int e = blockIdx.x * 256 + threadIdx.x;
    float m = mask[src[e]] * mask[dst[e]];
    if (m != 0.f) atomicAdd(&deg[dst[e]], w[e] * m);
}
__global__ void k_fin_dis(float* d) {       // deg >= 1 here
    int i = blockIdx.x * 256 + threadIdx.x;
    d[i] = rsqrtf(d[i]);
}
__global__ void k_fin_dis3(float* d) {
    int i = blockIdx.x * 256 + threadIdx.x;
    float v = d[i];
    d[i] = (v > 0.f) ? rsqrtf(fmaxf(v, 1e-12f)) : 0.f;
}

// ---------------- GEMM1: [N,400] @ [400,64] ----------------
// block = 256 threads, 32 rows per block; full W (400x64) in SMEM.
constexpr int G1_ROWS = 32;
constexpr int G1_XPAD = 404;   // row stride for x tile (bank-conflict-avoiding)
constexpr int SMEM_GEMM1 = (CIN * H + G1_ROWS * G1_XPAD) * 4;

__global__ void gemm1_kernel(const float* __restrict__ x, const float* __restrict__ W,
                             float* __restrict__ out) {
    extern __shared__ float sm[];
    float* Ws = sm;                    // [400*64]
    float* xs = sm + CIN * H;          // [32 * 404]
    const int tid = threadIdx.x;
    const int rowbase = blockIdx.x * G1_ROWS;

    for (int i = tid * 4; i < CIN * H; i += 1024)
        *(float4*)&Ws[i] = *(const float4*)&W[i];
    for (int i = tid * 4; i < G1_ROWS * CIN; i += 1024) {
        int r = i / CIN, k = i % CIN;   // CIN%4==0 so float4 never crosses rows
        *(float4*)&xs[r * G1_XPAD + k] = *(const float4*)&x[(size_t)(rowbase + r) * CIN + k];
    }
    __syncthreads();

    const int r  = tid >> 3;
    const int c0 = (tid & 7) * 8;
    float acc[8] = {0.f,0.f,0.f,0.f,0.f,0.f,0.f,0.f};
    const float* xr = &xs[r * G1_XPAD];
    #pragma unroll 4
    for (int k = 0; k < CIN; k += 4) {
        float4 xv = *(float4*)&xr[k];
        #pragma unroll
        for (int kk = 0; kk < 4; kk++) {
            float xk = (&xv.x)[kk];
            float4 w0 = *(float4*)&Ws[(k + kk) * H + c0];
            float4 w1 = *(float4*)&Ws[(k + kk) * H + c0 + 4];
            acc[0] = fmaf(xk, w0.x, acc[0]); acc[1] = fmaf(xk, w0.y, acc[1]);
            acc[2] = fmaf(xk, w0.z, acc[2]); acc[3] = fmaf(xk, w0.w, acc[3]);
            acc[4] = fmaf(xk, w1.x, acc[4]); acc[5] = fmaf(xk, w1.y, acc[5]);
            acc[6] = fmaf(xk, w1.z, acc[6]); acc[7] = fmaf(xk, w1.w, acc[7]);
        }
    }
    float* o = &out[(size_t)(rowbase + r) * H + c0];
    *(float4*)&o[0] = make_float4(acc[0], acc[1], acc[2], acc[3]);
    *(float4*)&o[4] = make_float4(acc[4], acc[5], acc[6], acc[7]);
}

// ---------------- small GEMM: [N,64] @ [64,CO], optional per-row scale ----------------
template<int CO>
__global__ void gemm_small_kernel(const float* __restrict__ X, const float* __restrict__ W,
                                  const float* __restrict__ rowscale, float* __restrict__ out) {
    constexpr int ROWS = 2048 / CO;   // 32 (CO=64) or 16 (CO=128)
    constexpr int CG   = CO / 8;
    __shared__ float Ws[H * CO];
    __shared__ float xs[ROWS][H + 4];
    const int tid = threadIdx.x;
    const int rowbase = blockIdx.x * ROWS;

    for (int i = tid * 4; i < H * CO; i += 1024)
        *(float4*)&Ws[i] = *(const float4*)&W[i];
    for (int i = tid * 4; i < ROWS * H; i += 1024) {
        int r = i >> 6, k = i & 63;
        *(float4*)&xs[r][k] = *(const float4*)&X[(size_t)(rowbase + r) * H + k];
    }
    __syncthreads();

    const int r  = tid / CG;
    const int c0 = (tid % CG) * 8;
    float acc[8] = {0.f,0.f,0.f,0.f,0.f,0.f,0.f,0.f};
    #pragma unroll 4
    for (int k = 0; k < H; k += 4) {
        float4 xv = *(float4*)&xs[r][k];
        #pragma unroll
        for (int kk = 0; kk < 4; kk++) {
            float xk = (&xv.x)[kk];
            float4 w0 = *(float4*)&Ws[(k + kk) * CO + c0];
            float4 w1 = *(float4*)&Ws[(k + kk) * CO + c0 + 4];
            acc[0] = fmaf(xk, w0.x, acc[0]); acc[1] = fmaf(xk, w0.y, acc[1]);
            acc[2] = fmaf(xk, w0.z, acc[2]); acc[3] = fmaf(xk, w0.w, acc[3]);
            acc[4] = fmaf(xk, w1.x, acc[4]); acc[5] = fmaf(xk, w1.y, acc[5]);
            acc[6] = fmaf(xk, w1.z, acc[6]); acc[7] = fmaf(xk, w1.w, acc[7]);
        }
    }
    float rs = rowscale ? rowscale[rowbase + r] : 1.f;
    float* o = &out[(size_t)(rowbase + r) * CO + c0];
    *(float4*)&o[0] = make_float4(acc[0]*rs, acc[1]*rs, acc[2]*rs, acc[3]*rs);
    *(float4*)&o[4] = make_float4(acc[4]*rs, acc[5]*rs, acc[6]*rs, acc[7]*rs);
}

// ---------------- per-graph aggregation (H=64), fused +bias, BN, ReLU ----------------
// smem: ysm[400*64] dsm[400] cn[400] sc[512] bsrc[8000]u16 bw[8000]f32
constexpr int SMEM_AGG64 = (NPG*H + NPG)*4 + (NPG + 512)*4 + EPG*2 + EPG*4;

__global__ void agg_h64_kernel(const float* __restrict__ xw, const float* __restrict__ dis,
                               const int* __restrict__ src, const int* __restrict__ dstp,
                               const float* __restrict__ ew,
                               const float* __restrict__ bias, const float* __restrict__ gam,
                               const float* __restrict__ bet, float* __restrict__ out) {
    extern __shared__ float sm[];
    float* ysm = sm;
    float* dsm = ysm + NPG * H;
    int*   cn  = (int*)(dsm + NPG);
    int*   sc  = cn + NPG;
    unsigned short* bsrc = (unsigned short*)(sc + 512);
    float* bw  = (float*)(bsrc + EPG);

    const int g = blockIdx.x;
    const int nb = g * NPG;
    const int eb = g * EPG;
    const int tid = threadIdx.x;

    for (int i = tid; i < NPG; i += 256) { dsm[i] = dis[nb + i]; cn[i] = 0; }
    __syncthreads();

    // ysm = dis[src-node] * xW
    for (int i = tid * 4; i < NPG * H; i += 1024) {
        int node = i >> 6;
        float4 v = *(const float4*)&xw[(size_t)(nb + node) * H + (i & 63)];
        float d = dsm[node];
        v.x *= d; v.y *= d; v.z *= d; v.w *= d;
        *(float4*)&ysm[i] = v;
    }
    // count edges per local dst
    for (int e = tid; e < EPG; e += 256)
        atomicAdd(&cn[dstp[eb + e] - nb], 1);
    __syncthreads();

    // inclusive scan of counts -> sc
    sc[tid] = cn[tid];
    sc[tid + 256] = (tid + 256 < NPG) ? cn[tid + 256] : 0;
    __syncthreads();
    for (int off = 1; off < 512; off <<= 1) {
        int a0 = sc[tid],       b0 = (tid >= off)       ? sc[tid - off]       : 0;
        int a1 = sc[tid + 256], b1 = (tid + 256 >= off) ? sc[tid + 256 - off] : 0;
        __syncthreads();
        sc[tid] = a0 + b0; sc[tid + 256] = a1 + b1;
        __syncthreads();
    }
    for (int i = tid; i < NPG; i += 256) cn[i] = 0;   // reuse as cursor
    __syncthreads();

    // scatter edges into dst buckets
    for (int e = tid; e < EPG; e += 256) {
        int sl = src[eb + e] - nb;
        int dl = dstp[eb + e] - nb;
        int pos = (dl ? sc[dl - 1] : 0) + atomicAdd(&cn[dl], 1);
        bsrc[pos] = (unsigned short)sl;
        bw[pos]   = ew[eb + e];
    }
    __syncthreads();

    // warp per dst node; lane owns feats {lane, lane+32}
    const int lane = tid & 31;
    const int warp = tid >> 5;
    const float s0 = gam[lane] * BN_RS,      s1 = gam[lane + 32] * BN_RS;
    const float t0 = bet[lane],              t1 = bet[lane + 32];
    const float bb0 = bias[lane],            bb1 = bias[lane + 32];
    for (int dl = warp; dl < NPG; dl += 8) {
        int e0 = dl ? sc[dl - 1] : 0;
        int e1 = sc[dl];
        float a0 = ysm[dl * H + lane];        // self-loop term (dis*xw)
        float a1 = ysm[dl * H + lane + 32];
        for (int j = e0; j < e1; j++) {
            int sl = bsrc[j];
            float w = bw[j];
            a0 = fmaf(w, ysm[sl * H + lane],      a0);
            a1 = fmaf(w, ysm[sl * H + lane + 32], a1);
        }
        float d = dsm[dl];
        float v0 = fmaf(d, a0, bb0);
        float v1 = fmaf(d, a1, bb1);
        v0 = fmaxf(fmaf(v0, s0, t0), 0.f);
        v1 = fmaxf(fmaf(v1, s1, t1), 0.f);
        size_t o = (size_t)(nb + dl) * H;
        out[o + lane] = v0;
        out[o + lane + 32] = v1;
    }
}

// ---------------- per-graph aggregation layer 3 (H3=128, masked edges) ----------------
// smem: ysm[400*64] dsm[400] msm[400] cn[400] sc[512] bsrc[8000]u16 bw[8000]f32
constexpr int SMEM_AGG128 = (NPG*H + 2*NPG)*4 + (NPG + 512)*4 + EPG*2 + EPG*4;

__global__ void agg_h128_kernel(const float* __restrict__ xw, const float* __restrict__ dis3,
                                const float* __restrict__ mask,
                                const int* __restrict__ src, const int* __restrict__ dstp,
                                const float* __restrict__ ew,
                                const float* __restrict__ bias, const float* __restrict__ gam,
                                const float* __restrict__ bet, float* __restrict__ out) {
    extern __shared__ float sm[];
    float* ysm = sm;
    float* dsm = ysm + NPG * H;
    float* msm = dsm + NPG;
    int*   cn  = (int*)(msm + NPG);
    int*   sc  = cn + NPG;
    unsigned short* bsrc = (unsigned short*)(sc + 512);
    float* bw  = (float*)(bsrc + EPG);

    const int g = blockIdx.x;
    const int nb = g * NPG;
    const int eb = g * EPG;
    const int tid = threadIdx.x;

    for (int i = tid; i < NPG; i += 256) {
        dsm[i] = dis3[nb + i];
        msm[i] = mask[nb + i];
        cn[i] = 0;
    }
    __syncthreads();

    // count only surviving edges (both endpoints kept)
    for (int e = tid; e < EPG; e += 256) {
        int sl = src[eb + e] - nb;
        int dl = dstp[eb + e] - nb;
        if (msm[sl] != 0.f && msm[dl] != 0.f) atomicAdd(&cn[dl], 1);
    }
    __syncthreads();
    sc[tid] = cn[tid];
    sc[tid + 256] = (tid + 256 < NPG) ? cn[tid + 256] : 0;
    __syncthreads();
    for (int off = 1; off < 512; off <<= 1) {
        int a0 = sc[tid],       b0 = (tid >= off)       ? sc[tid - off]       : 0;
        int a1 = sc[tid + 256], b1 = (tid + 256 >= off) ? sc[tid + 256 - off] : 0;
        __syncthreads();
        sc[tid] = a0 + b0; sc[tid + 256] = a1 + b1;
        __syncthreads();
    }
    for (int i = tid; i < NPG; i += 256) cn[i] = 0;
    __syncthreads();
    for (int e = tid; e < EPG; e += 256) {
        int sl = src[eb + e] - nb;
        int dl = dstp[eb + e] - nb;
        if (msm[sl] != 0.f && msm[dl] != 0.f) {
            int pos = (dl ? sc[dl - 1] : 0) + atomicAdd(&cn[dl], 1);
            bsrc[pos] = (unsigned short)sl;
            bw[pos]   = ew[eb + e];          // mask product == 1 for kept edges
        }
    }

    const int lane = tid & 31;
    const int warp = tid >> 5;
    #pragma unroll
    for (int hf = 0; hf < 2; hf++) {
        __syncthreads();
        // ysm = dis3 * xw3[:, hf*64 : hf*64+64]
        for (int i = tid * 4; i < NPG * H; i += 1024) {
            int node = i >> 6;
            float4 v = *(const float4*)&xw[(size_t)(nb + node) * H3 + hf * H + (i & 63)];
            float d = dsm[node];
            v.x *= d; v.y *= d; v.z *= d; v.w *= d;
            *(float4*)&ysm[i] = v;
        }
        __syncthreads();
        const int f0 = hf * H + lane, f1 = hf * H + lane + 32;
        const float s0 = gam[f0] * BN_RS, s1 = gam[f1] * BN_RS;
        const float t0 = bet[f0],         t1 = bet[f1];
        const float bb0 = bias[f0],       bb1 = bias[f1];
        for (int dl = warp; dl < NPG; dl += 8) {
            int e0 = dl ? sc[dl - 1] : 0;
            int e1 = sc[dl];
            float m = msm[dl];
            float a0 = m * ysm[dl * H + lane];       // self-loop has weight = mask
            float a1 = m * ysm[dl * H + lane + 32];
            for (int j = e0; j < e1; j++) {
                int sl = bsrc[j];
                float w = bw[j];
                a0 = fmaf(w, ysm[sl * H + lane],      a0);
                a1 = fmaf(w, ysm[sl * H + lane + 32], a1);
            }
            float d = dsm[dl];
            float v0 = fmaf(d, a0, bb0);
            float v1 = fmaf(d, a1, bb1);
            v0 = fmaxf(fmaf(v0, s0, t0), 0.f);
            v1 = fmaxf(fmaf(v1, s1, t1), 0.f);
            size_t o = (size_t)(nb + dl) * H3;
            out[o + f0] = v0;
            out[o + f1] = v1;
        }
    }
}

// ---------------- pooling score: tanh((h.p)/||p||) ----------------
__global__ void score_kernel(const float* __restrict__ h, const float* __restrict__ p,
                             float* __restrict__ score) {
    int node = blockIdx.x * 8 + (threadIdx.x >> 5);
    int lane = threadIdx.x & 31;
    float p0 = p[lane], p1 = p[lane + 32];
    float pn = p0 * p0 + p1 * p1;
    float d = h[(size_t)node * H + lane] * p0 + h[(size_t)node * H + lane + 32] * p1;
    #pragma unroll
    for (int o = 16; o; o >>= 1) {
        pn += __shfl_xor_sync(0xffffffffu, pn, o);
        d  += __shfl_xor_sync(0xffffffffu, d,  o);
    }
    if (lane == 0) score[node] = tanhf(d * rsqrtf(pn));
}

// ---------------- top-k (200 of 400) per graph ----------------
__global__ void topk_kernel(const float* __restrict__ score, float* __restrict__ mask,
                            float* __restrict__ gate) {
    __shared__ float s[512];
    __shared__ float orig[NPG];
    __shared__ unsigned char km[NPG];
    __shared__ int cnt;
    const int g = blockIdx.x, tid = threadIdx.x;
    for (int i = tid; i < 512; i += 256) {
        float v = (i < NPG) ? score[g * NPG + i] : -INFINITY;
        s[i] = v;
        if (i < NPG) orig[i] = v;
    }
    if (tid == 0) cnt = 0;
    __syncthreads();
    // bitonic sort ascending
    for (int k = 2; k <= 512; k <<= 1) {
        for (int j = k >> 1; j > 0; j >>= 1) {
            for (int t = tid; t < 512; t += 256) {
                int ixj = t ^ j;
                if (ixj > t) {
                    float a = s[t], b = s[ixj];
                    bool sw = ((t & k) == 0) ? (a > b) : (a < b);
                    if (sw) { s[t] = b; s[ixj] = a; }
                }
            }
            __syncthreads();
        }
    }
    float thr = s[512 - KEEP];      // 200th largest
    int local = 0;
    for (int i = tid; i < NPG; i += 256)
        if (orig[i] > thr) local++;
    atomicAdd(&cnt, local);
    __syncthreads();
    if (tid == 0) {  // tie-break: lowest index first (matches lax.top_k)
        int rem = KEEP - cnt;
        for (int i = 0; i < NPG; i++) {
            unsigned char m = (orig[i] > thr) ? 1 : 0;
            if (!m && orig[i] == thr && rem > 0) { m = 1; rem--; }
            km[i] = m;
        }
    }
    __syncthreads();
    for (int i = tid; i < NPG; i += 256) {
        float m = km[i] ? 1.f : 0.f;
        mask[g * NPG + i] = m;
        gate[g * NPG + i] = m * orig[i];
    }
}

// ---------------- readout: per-graph masked mean/max over H3 feats ----------------
__global__ void readout_kernel(const float* __restrict__ h3, const float* __restrict__ mask,
                               float* __restrict__ emb) {
    __shared__ float msm[NPG];
    const int g = blockIdx.x, f = threadIdx.x;   // 128 threads
    for (int i = f; i < NPG; i += 128) msm[i] = mask[g * NPG + i];
    __syncthreads();
    float sum = 0.f, mx = -INFINITY;
    const float* base = &h3[(size_t)g * NPG * H3 + f];
    for (int i = 0; i < NPG; i++) {
        if (msm[i] != 0.f) {
            float v = base[(size_t)i * H3];
            sum += v;
            mx = fmaxf(mx, v);
        }
    }
    emb[g * 4 * H + f]      = sum * (1.f / KEEP);
    emb[g * 4 * H + H3 + f] = mx;
}

// ---------------- MLP head ----------------
__global__ void head_kernel(const float* __restrict__ emb,
                            const float* __restrict__ f1w, const float* __restrict__ f1b,
                            const float* __restrict__ gfc, const float* __restrict__ bfc,
                            const float* __restrict__ f2w, const float* __restrict__ f2b,
                            float* __restrict__ out) {
    __shared__ float z[64];
    const int g = blockIdx.x, j = threadIdx.x;   // 64 threads
    float acc = f1b[j];
    const float* e = &emb[g * 256];
    #pragma unroll 8
    for (int k = 0; k < 256; k++)
        acc = fmaf(e[k], f1w[k * 64 + j], acc);
    acc = fmaf(acc, gfc[j] * BN_RS, bfc[j]);
    z[j] = fmaxf(acc, 0.f);
    __syncthreads();
    if (j < 2) {
        float o = f2b[j];
        for (int k = 0; k < 64; k++)
            o = fmaf(z[k], f2w[k * 2 + j], o);
        out[g * 2 + j] = o;
    }
}

// ---------------- launch ----------------
extern "C" void kernel_launch(void* const* d_in, const int* in_sizes, int n_in,
                              void* d_out, int out_size) {
    const float* x   = (const float*)d_in[0];
    const int*   ei  = (const int*)  d_in[1];
    const float* ew  = (const float*)d_in[2];
    // d_in[3] = batch (layout is known, unused)
    const float* W1  = (const float*)d_in[4];
    const float* b1  = (const float*)d_in[5];
    const float* g1  = (const float*)d_in[6];
    const float* bt1 = (const float*)d_in[7];
    const float* W2  = (const float*)d_in[8];
    const float* b2  = (const float*)d_in[9];
    const float* g2  = (const float*)d_in[10];
    const float* bt2 = (const float*)d_in[11];
    const float* pp  = (const float*)d_in[12];
    const float* W3  = (const float*)d_in[13];
    const float* b3  = (const float*)d_in[14];
    const float* g3  = (const float*)d_in[15];
    const float* bt3 = (const float*)d_in[16];
    const float* f1w = (const float*)d_in[17];
    const float* f1b = (const float*)d_in[18];
    const float* gfc = (const float*)d_in[19];
    const float* bfc = (const float*)d_in[20];
    const float* f2w = (const float*)d_in[21];
    const float* f2b = (const float*)d_in[22];
    float* out = (float*)d_out;

    const int* src = ei;
    const int* dst = ei + Etot;

    float *p_xw1, *p_h1, *p_xw2, *p_h2, *p_xw3, *p_h3;
    float *p_dis, *p_dis3, *p_score, *p_mask, *p_gate, *p_emb;
    cudaGetSymbolAddress((void**)&p_xw1,  g_xw1);
    cudaGetSymbolAddress((void**)&p_h1,   g_h1);
    cudaGetSymbolAddress((void**)&p_xw2,  g_xw2);
    cudaGetSymbolAddress((void**)&p_h2,   g_h2);
    cudaGetSymbolAddress((void**)&p_xw3,  g_xw3);
    cudaGetSymbolAddress((void**)&p_h3,   g_h3);
    cudaGetSymbolAddress((void**)&p_dis,  g_dis);
    cudaGetSymbolAddress((void**)&p_dis3, g_dis3);
    cudaGetSymbolAddress((void**)&p_score,g_score);
    cudaGetSymbolAddress((void**)&p_mask, g_mask);
    cudaGetSymbolAddress((void**)&p_gate, g_gate);
    cudaGetSymbolAddress((void**)&p_emb,  g_emb);

    cudaFuncSetAttribute(gemm1_kernel,   cudaFuncAttributeMaxDynamicSharedMemorySize, SMEM_GEMM1);
    cudaFuncSetAttribute(agg_h64_kernel, cudaFuncAttributeMaxDynamicSharedMemorySize, SMEM_AGG64);
    cudaFuncSetAttribute(agg_h128_kernel,cudaFuncAttributeMaxDynamicSharedMemorySize, SMEM_AGG128);

    const int NB = Ntot / 256;   // 400
    const int EB = Etot / 256;   // 8000

    // layer-1/2 symmetric normalization
    k_fill<<<NB, 256>>>(p_dis, 1.0f);
    k_accum_deg<<<EB, 256>>>(dst, ew, p_dis);
    k_fin_dis<<<NB, 256>>>(p_dis);

    // GCN1
    gemm1_kernel<<<Ntot / G1_ROWS, 256, SMEM_GEMM1>>>(x, W1, p_xw1);
    agg_h64_kernel<<<Bg, 256, SMEM_AGG64>>>(p_xw1, p_dis, src, dst, ew, b1, g1, bt1, p_h1);

    // GCN2
    gemm_small_kernel<64><<<Ntot / 32, 256>>>(p_h1, W2, nullptr, p_xw2);
    agg_h64_kernel<<<Bg, 256, SMEM_AGG64>>>(p_xw2, p_dis, src, dst, ew, b2, g2, bt2, p_h2);

    // TopK pooling
    score_kernel<<<Ntot / 8, 256>>>(p_h2, pp, p_score);
    topk_kernel<<<Bg, 256>>>(p_score, p_mask, p_gate);

    // layer-3 normalization over surviving edges (self-loop weight = mask)
    k_copy<<<NB, 256>>>(p_dis3, p_mask);
    k_accum_deg3<<<EB, 256>>>(src, dst, ew, p_mask, p_dis3);
    k_fin_dis3<<<NB, 256>>>(p_dis3);

    // GCN3 (input gated by score*mask)
    gemm_small_kernel<128><<<Ntot / 16, 256>>>(p_h2, W3, p_gate, p_xw3);
    agg_h128_kernel<<<Bg, 256, SMEM_AGG128>>>(p_xw3, p_dis3, p_mask, src, dst, ew,
                                              b3, g3, bt3, p_h3);

    // readout + head
    readout_kernel<<<Bg, 128>>>(p_h3, p_mask, p_emb);
    head_kernel<<<Bg, 64>>>(p_emb, f1w, f1b, gfc, bfc, f2w, f2b, out);
}

// round 6
// speedup vs baseline: 2.3441x; 2.3441x over previous
#include <cuda_runtime.h>
#include <cuda_bf16.h>
#include <mma.h>
#include <math.h>
#include <stdint.h>

using namespace nvcuda;

// ---------------- problem constants ----------------
constexpr int Bg   = 256;     // graphs
constexpr int NPG  = 400;     // nodes per graph
constexpr int Ntot = Bg * NPG;        // 102400
constexpr int EPG  = 8000;    // edges per graph
constexpr int Etot = Bg * EPG;        // 2048000
constexpr int CIN  = 400;
constexpr int H    = 64;
constexpr int H3   = 128;
constexpr int KEEP = 200;
#define BN_RS 0.99999500003749968f  /* rsqrt(1+1e-5) */

// ---------------- scratch (device globals; no allocation allowed) ----------------
__device__ float g_xw1[Ntot * H];
__device__ float g_h1 [Ntot * H];
__device__ float g_xw2[Ntot * H];
__device__ float g_h2 [Ntot * H];
__device__ float g_xw3[Ntot * H3];
__device__ float g_h3 [Ntot * H3];
__device__ float g_dis [Ntot];
__device__ float g_dis3[Ntot];
__device__ float g_score[Ntot];
__device__ float g_mask[Ntot];
__device__ float g_gate[Ntot];
__device__ float g_emb[Bg * 4 * H];   // [B, 256]
// split bf16 weights, row-major [KPAD][CO]
__device__ __nv_bfloat16 g_w1h[448 * 64];
__device__ __nv_bfloat16 g_w1l[448 * 64];
__device__ __nv_bfloat16 g_w2h[64 * 64];
__device__ __nv_bfloat16 g_w2l[64 * 64];
__device__ __nv_bfloat16 g_w3h[64 * 128];
__device__ __nv_bfloat16 g_w3l[64 * 128];

__device__ __forceinline__ uint32_t pack_bf2(__nv_bfloat16 a, __nv_bfloat16 b) {
    __nv_bfloat162 t = __halves2bfloat162(a, b);
    return *reinterpret_cast<uint32_t*>(&t);
}

// ---------------- weight bf16 split (no transpose; pad K rows) ----------------
__global__ void wconv_kernel(const float* __restrict__ W, __nv_bfloat16* __restrict__ hi,
                             __nv_bfloat16* __restrict__ lo,
                             int KDIM, int CO, int total) {
    int i = blockIdx.x * 256 + threadIdx.x;
    if (i >= total) return;
    int k = i / CO;
    float v = (k < KDIM) ? W[i] : 0.f;
    __nv_bfloat16 h = __float2bfloat16(v);
    hi[i] = h;
    lo[i] = __float2bfloat16(v - __bfloat162float(h));
}

// ---------------- wmma bf16x3 GEMM: out[M,CO] = X[M,KDIM] @ W[KDIM,CO] ----------------
// 256 threads (8 warps), 128 rows per CTA, K in 64-wide chunks.
template<int CO, int KDIM, bool SCALE>
__global__ void __launch_bounds__(256) wgemm_kernel(
        const float* __restrict__ X,
        const __nv_bfloat16* __restrict__ wh,
        const __nv_bfloat16* __restrict__ wl,
        const float* __restrict__ rowscale,
        float* __restrict__ out) {
    constexpr int KCH = (KDIM + 63) / 64;
    constexpr int LDA = 72;
    constexpr int LDB = CO + 8;
    constexpr int NT  = CO / 16;

    extern __shared__ char smraw[];
    __nv_bfloat16* Ah = (__nv_bfloat16*)smraw;      // 128*LDA
    __nv_bfloat16* Al = Ah + 128 * LDA;
    __nv_bfloat16* Bh = Al + 128 * LDA;             // 64*LDB
    __nv_bfloat16* Bl = Bh + 64 * LDB;
    float* sOut = (float*)smraw;                    // union: 128*LDB floats

    const int tid  = threadIdx.x;
    const int warp = tid >> 5;
    const int rb   = blockIdx.x * 128;

    wmma::fragment<wmma::accumulator, 16, 16, 16, float> acc[NT];
    #pragma unroll
    for (int t = 0; t < NT; t++) wmma::fill_fragment(acc[t], 0.f);

    for (int ch = 0; ch < KCH; ch++) {
        const int kb = ch * 64;
        __syncthreads();
        // A chunk: 128x64 fp32 -> bf16 hi/lo
        #pragma unroll 2
        for (int i = tid * 4; i < 128 * 64; i += 1024) {
            int r = i >> 6, c = i & 63;
            float4 v = make_float4(0.f, 0.f, 0.f, 0.f);
            if ((KDIM & 63) == 0 || kb + c < KDIM)
                v = *(const float4*)&X[(size_t)(rb + r) * KDIM + kb + c];
            __nv_bfloat16 h0 = __float2bfloat16(v.x);
            __nv_bfloat16 h1 = __float2bfloat16(v.y);
            __nv_bfloat16 h2 = __float2bfloat16(v.z);
            __nv_bfloat16 h3 = __float2bfloat16(v.w);
            __nv_bfloat16 l0 = __float2bfloat16(v.x - __bfloat162float(h0));
            __nv_bfloat16 l1 = __float2bfloat16(v.y - __bfloat162float(h1));
            __nv_bfloat16 l2 = __float2bfloat16(v.z - __bfloat162float(h2));
            __nv_bfloat16 l3 = __float2bfloat16(v.w - __bfloat162float(h3));
            *(uint2*)&Ah[r * LDA + c] = make_uint2(pack_bf2(h0, h1), pack_bf2(h2, h3));
            *(uint2*)&Al[r * LDA + c] = make_uint2(pack_bf2(l0, l1), pack_bf2(l2, l3));
        }
        // B chunk: 64 x CO bf16 (pre-split)
        #pragma unroll 2
        for (int i = tid * 4; i < 64 * CO; i += 1024) {
            int r = i / CO, c = i & (CO - 1);
            *(uint2*)&Bh[r * LDB + c] = *(const uint2*)&wh[(size_t)(kb + r) * CO + c];
            *(uint2*)&Bl[r * LDB + c] = *(const uint2*)&wl[(size_t)(kb + r) * CO + c];
        }
        __syncthreads();

        const __nv_bfloat16* arow_h = Ah + (warp * 16) * LDA;
        const __nv_bfloat16* arow_l = Al + (warp * 16) * LDA;
        #pragma unroll
        for (int k16 = 0; k16 < 4; k16++) {
            wmma::fragment<wmma::matrix_a, 16, 16, 16, __nv_bfloat16, wmma::row_major> fa_h, fa_l;
            wmma::load_matrix_sync(fa_h, arow_h + k16 * 16, LDA);
            wmma::load_matrix_sync(fa_l, arow_l + k16 * 16, LDA);
            #pragma unroll
            for (int t = 0; t < NT; t++) {
                wmma::fragment<wmma::matrix_b, 16, 16, 16, __nv_bfloat16, wmma::row_major> fb_h, fb_l;
                wmma::load_matrix_sync(fb_h, Bh + (k16 * 16) * LDB + t * 16, LDB);
                wmma::load_matrix_sync(fb_l, Bl + (k16 * 16) * LDB + t * 16, LDB);
                wmma::mma_sync(acc[t], fa_h, fb_h, acc[t]);
                wmma::mma_sync(acc[t], fa_h, fb_l, acc[t]);
                wmma::mma_sync(acc[t], fa_l, fb_h, acc[t]);
            }
        }
    }
    __syncthreads();
    #pragma unroll
    for (int t = 0; t < NT; t++)
        wmma::store_matrix_sync(sOut + (warp * 16) * LDB + t * 16, acc[t], LDB,
                                wmma::mem_row_major);
    __syncthreads();
    #pragma unroll 2
    for (int i = tid * 4; i < 128 * CO; i += 1024) {
        int r = i / CO, c = i & (CO - 1);
        float4 v = *(float4*)&sOut[r * LDB + c];
        float rs = 1.f;
        if (SCALE) rs = rowscale[rb + r];
        v.x *= rs; v.y *= rs; v.z *= rs; v.w *= rs;
        *(float4*)&out[(size_t)(rb + r) * CO + c] = v;
    }
}

constexpr int wg_smem(int CO) {
    int lda = 72, ldb = CO + 8;
    int ab = (2 * 128 * lda + 2 * 64 * ldb) * 2;
    int os = 128 * ldb * 4;
    return ab > os ? ab : os;
}

// ---------------- degree / dis kernels ----------------
__global__ void k_fill(float* p, float v) {
    int i = blockIdx.x * 256 + threadIdx.x;
    p[i] = v;
}
__global__ void k_copy(float* dstp, const float* srcp) {
    int i = blockIdx.x * 256 + threadIdx.x;
    dstp[i] = srcp[i];
}
__global__ void k_accum_deg(const int* __restrict__ dst, const float* __restrict__ w,
                            float* __restrict__ deg) {
    int e = blockIdx.x * 256 + threadIdx.x;
    atomicAdd(&deg[dst[e]], w[e]);
}
__global__ void k_accum_deg3(const int* __restrict__ src, const int* __restrict__ dst,
                             const float* __restrict__ w, const float* __restrict__ mask,
                             float* __restrict__ deg) {
    int e = blockIdx.x * 256 + threadIdx.x;
    float m = mask[src[e]] * mask[dst[e]];
    if (m != 0.f) atomicAdd(&deg[dst[e]], w[e] * m);
}
__global__ void k_fin_dis(float* d) {
    int i = blockIdx.x * 256 + threadIdx.x;
    d[i] = rsqrtf(d[i]);
}
__global__ void k_fin_dis3(float* d) {
    int i = blockIdx.x * 256 + threadIdx.x;
    float v = d[i];
    d[i] = (v > 0.f) ? rsqrtf(fmaxf(v, 1e-12f)) : 0.f;
}

// ---------------- per-graph aggregation (H=64), fused +bias, BN, ReLU ----------------
constexpr int SMEM_AGG64 = (NPG*H + NPG)*4 + (NPG + 512)*4 + EPG*2 + EPG*4;

__global__ void agg_h64_kernel(const float* __restrict__ xw, const float* __restrict__ dis,
                               const int* __restrict__ src, const int* __restrict__ dstp,
                               const float* __restrict__ ew,
                               const float* __restrict__ bias, const float* __restrict__ gam,
                               const float* __restrict__ bet, float* __restrict__ out) {
    extern __shared__ float smf[];
    float* ysm = smf;
    float* dsm = ysm + NPG * H;
    int*   cn  = (int*)(dsm + NPG);
    int*   sc  = cn + NPG;
    unsigned short* bsrc = (unsigned short*)(sc + 512);
    float* bw  = (float*)(bsrc + EPG);

    const int g = blockIdx.x;
    const int nb = g * NPG;
    const int eb = g * EPG;
    const int tid = threadIdx.x;

    for (int i = tid; i < NPG; i += 256) { dsm[i] = dis[nb + i]; cn[i] = 0; }
    __syncthreads();

    for (int i = tid * 4; i < NPG * H; i += 1024) {
        int node = i >> 6;
        float4 v = *(const float4*)&xw[(size_t)(nb + node) * H + (i & 63)];
        float d = dsm[node];
        v.x *= d; v.y *= d; v.z *= d; v.w *= d;
        *(float4*)&ysm[i] = v;
    }
    for (int e = tid; e < EPG; e += 256)
        atomicAdd(&cn[dstp[eb + e] - nb], 1);
    __syncthreads();

    sc[tid] = cn[tid];
    sc[tid + 256] = (tid + 256 < NPG) ? cn[tid + 256] : 0;
    __syncthreads();
    for (int off = 1; off < 512; off <<= 1) {
        int a0 = sc[tid],       b0 = (tid >= off)       ? sc[tid - off]       : 0;
        int a1 = sc[tid + 256], b1 = (tid + 256 >= off) ? sc[tid + 256 - off] : 0;
        __syncthreads();
        sc[tid] = a0 + b0; sc[tid + 256] = a1 + b1;
        __syncthreads();
    }
    for (int i = tid; i < NPG; i += 256) cn[i] = 0;
    __syncthreads();

    for (int e = tid; e < EPG; e += 256) {
        int sl = src[eb + e] - nb;
        int dl = dstp[eb + e] - nb;
        int pos = (dl ? sc[dl - 1] : 0) + atomicAdd(&cn[dl], 1);
        bsrc[pos] = (unsigned short)sl;
        bw[pos]   = ew[eb + e];
    }
    __syncthreads();

    const int lane = tid & 31;
    const int warp = tid >> 5;
    const float s0 = gam[lane] * BN_RS,      s1 = gam[lane + 32] * BN_RS;
    const float t0 = bet[lane],              t1 = bet[lane + 32];
    const float bb0 = bias[lane],            bb1 = bias[lane + 32];
    for (int dl = warp; dl < NPG; dl += 8) {
        int e0 = dl ? sc[dl - 1] : 0;
        int e1 = sc[dl];
        float a0 = ysm[dl * H + lane];
        float a1 = ysm[dl * H + lane + 32];
        for (int j = e0; j < e1; j++) {
            int sl = bsrc[j];
            float w = bw[j];
            a0 = fmaf(w, ysm[sl * H + lane],      a0);
            a1 = fmaf(w, ysm[sl * H + lane + 32], a1);
        }
        float d = dsm[dl];
        float v0 = fmaf(d, a0, bb0);
        float v1 = fmaf(d, a1, bb1);
        v0 = fmaxf(fmaf(v0, s0, t0), 0.f);
        v1 = fmaxf(fmaf(v1, s1, t1), 0.f);
        size_t o = (size_t)(nb + dl) * H;
        out[o + lane] = v0;
        out[o + lane + 32] = v1;
    }
}

// ---------------- per-graph aggregation layer 3 (H3=128, masked edges) ----------------
constexpr int SMEM_AGG128 = (NPG*H + 2*NPG)*4 + (NPG + 512)*4 + EPG*2 + EPG*4;

__global__ void agg_h128_kernel(const float* __restrict__ xw, const float* __restrict__ dis3,
                                const float* __restrict__ mask,
                                const int* __restrict__ src, const int* __restrict__ dstp,
                                const float* __restrict__ ew,
                                const float* __restrict__ bias, const float* __restrict__ gam,
                                const float* __restrict__ bet, float* __restrict__ out) {
    extern __shared__ float smf[];
    float* ysm = smf;
    float* dsm = ysm + NPG * H;
    float* msm = dsm + NPG;
    int*   cn  = (int*)(msm + NPG);
    int*   sc  = cn + NPG;
    unsigned short* bsrc = (unsigned short*)(sc + 512);
    float* bw  = (float*)(bsrc + EPG);

    const int g = blockIdx.x;
    const int nb = g * NPG;
    const int eb = g * EPG;
    const int tid = threadIdx.x;

    for (int i = tid; i < NPG; i += 256) {
        dsm[i] = dis3[nb + i];
        msm[i] = mask[nb + i];
        cn[i] = 0;
    }
    __syncthreads();

    for (int e = tid; e < EPG; e += 256) {
        int sl = src[eb + e] - nb;
        int dl = dstp[eb + e] - nb;
        if (msm[sl] != 0.f && msm[dl] != 0.f) atomicAdd(&cn[dl], 1);
    }
    __syncthreads();
    sc[tid] = cn[tid];
    sc[tid + 256] = (tid + 256 < NPG) ? cn[tid + 256] : 0;
    __syncthreads();
    for (int off = 1; off < 512; off <<= 1) {
        int a0 = sc[tid],       b0 = (tid >= off)       ? sc[tid - off]       : 0;
        int a1 = sc[tid + 256], b1 = (tid + 256 >= off) ? sc[tid + 256 - off] : 0;
        __syncthreads();
        sc[tid] = a0 + b0; sc[tid + 256] = a1 + b1;
        __syncthreads();
    }
    for (int i = tid; i < NPG; i += 256) cn[i] = 0;
    __syncthreads();
    for (int e = tid; e < EPG; e += 256) {
        int sl = src[eb + e] - nb;
        int dl = dstp[eb + e] - nb;
        if (msm[sl] != 0.f && msm[dl] != 0.f) {
            int pos = (dl ? sc[dl - 1] : 0) + atomicAdd(&cn[dl], 1);
            bsrc[pos] = (unsigned short)sl;
            bw[pos]   = ew[eb + e];
        }
    }

    const int lane = tid & 31;
    const int warp = tid >> 5;
    #pragma unroll
    for (int hf = 0; hf < 2; hf++) {
        __syncthreads();
        for (int i = tid * 4; i < NPG * H; i += 1024) {
            int node = i >> 6;
            float4 v = *(const float4*)&xw[(size_t)(nb + node) * H3 + hf * H + (i & 63)];
            float d = dsm[node];
            v.x *= d; v.y *= d; v.z *= d; v.w *= d;
            *(float4*)&ysm[i] = v;
        }
        __syncthreads();
        const int f0 = hf * H + lane, f1 = hf * H + lane + 32;
        const float s0 = gam[f0] * BN_RS, s1 = gam[f1] * BN_RS;
        const float t0 = bet[f0],         t1 = bet[f1];
        const float bb0 = bias[f0],       bb1 = bias[f1];
        for (int dl = warp; dl < NPG; dl += 8) {
            int e0 = dl ? sc[dl - 1] : 0;
            int e1 = sc[dl];
            float m = msm[dl];
            float a0 = m * ysm[dl * H + lane];
            float a1 = m * ysm[dl * H + lane + 32];
            for (int j = e0; j < e1; j++) {
                int sl = bsrc[j];
                float w = bw[j];
                a0 = fmaf(w, ysm[sl * H + lane],      a0);
                a1 = fmaf(w, ysm[sl * H + lane + 32], a1);
            }
            float d = dsm[dl];
            float v0 = fmaf(d, a0, bb0);
            float v1 = fmaf(d, a1, bb1);
            v0 = fmaxf(fmaf(v0, s0, t0), 0.f);
            v1 = fmaxf(fmaf(v1, s1, t1), 0.f);
            size_t o = (size_t)(nb + dl) * H3;
            out[o + f0] = v0;
            out[o + f1] = v1;
        }
    }
}

// ---------------- pooling score: tanh((h.p)/||p||) ----------------
__global__ void score_kernel(const float* __restrict__ h, const float* __restrict__ p,
                             float* __restrict__ score) {
    int node = blockIdx.x * 8 + (threadIdx.x >> 5);
    int lane = threadIdx.x & 31;
    float p0 = p[lane], p1 = p[lane + 32];
    float pn = p0 * p0 + p1 * p1;
    float d = h[(size_t)node * H + lane] * p0 + h[(size_t)node * H + lane + 32] * p1;
    #pragma unroll
    for (int o = 16; o; o >>= 1) {
        pn += __shfl_xor_sync(0xffffffffu, pn, o);
        d  += __shfl_xor_sync(0xffffffffu, d,  o);
    }
    if (lane == 0) score[node] = tanhf(d * rsqrtf(pn));
}

// ---------------- top-k (200 of 400) per graph ----------------
__global__ void topk_kernel(const float* __restrict__ score, float* __restrict__ mask,
                            float* __restrict__ gate) {
    __shared__ float s[512];
    __shared__ float orig[NPG];
    __shared__ unsigned char km[NPG];
    __shared__ int cnt;
    const int g = blockIdx.x, tid = threadIdx.x;
    for (int i = tid; i < 512; i += 256) {
        float v = (i < NPG) ? score[g * NPG + i] : -INFINITY;
        s[i] = v;
        if (i < NPG) orig[i] = v;
    }
    if (tid == 0) cnt = 0;
    __syncthreads();
    for (int k = 2; k <= 512; k <<= 1) {
        for (int j = k >> 1; j > 0; j >>= 1) {
            for (int t = tid; t < 512; t += 256) {
                int ixj = t ^ j;
                if (ixj > t) {
                    float a = s[t], b = s[ixj];
                    bool sw = ((t & k) == 0) ? (a > b) : (a < b);
                    if (sw) { s[t] = b; s[ixj] = a; }
                }
            }
            __syncthreads();
        }
    }
    float thr = s[512 - KEEP];
    int local = 0;
    for (int i = tid; i < NPG; i += 256)
        if (orig[i] > thr) local++;
    atomicAdd(&cnt, local);
    __syncthreads();
    if (tid == 0) {
        int rem = KEEP - cnt;
        for (int i = 0; i < NPG; i++) {
            unsigned char m = (orig[i] > thr) ? 1 : 0;
            if (!m && orig[i] == thr && rem > 0) { m = 1; rem--; }
            km[i] = m;
        }
    }
    __syncthreads();
    for (int i = tid; i < NPG; i += 256) {
        float m = km[i] ? 1.f : 0.f;
        mask[g * NPG + i] = m;
        gate[g * NPG + i] = m * orig[i];
    }
}

// ---------------- readout ----------------
__global__ void readout_kernel(const float* __restrict__ h3, const float* __restrict__ mask,
                               float* __restrict__ emb) {
    __shared__ float msm[NPG];
    const int g = blockIdx.x, f = threadIdx.x;
    for (int i = f; i < NPG; i += 128) msm[i] = mask[g * NPG + i];
    __syncthreads();
    float sum = 0.f, mx = -INFINITY;
    const float* base = &h3[(size_t)g * NPG * H3 + f];
    for (int i = 0; i < NPG; i++) {
        if (msm[i] != 0.f) {
            float v = base[(size_t)i * H3];
            sum += v;
            mx = fmaxf(mx, v);
        }
    }
    emb[g * 4 * H + f]      = sum * (1.f / KEEP);
    emb[g * 4 * H + H3 + f] = mx;
}

// ---------------- MLP head ----------------
__global__ void head_kernel(const float* __restrict__ emb,
                            const float* __restrict__ f1w, const float* __restrict__ f1b,
                            const float* __restrict__ gfc, const float* __restrict__ bfc,
                            const float* __restrict__ f2w, const float* __restrict__ f2b,
                            float* __restrict__ out) {
    __shared__ float z[64];
    const int g = blockIdx.x, j = threadIdx.x;
    float acc = f1b[j];
    const float* e = &emb[g * 256];
    #pragma unroll 8
    for (int k = 0; k < 256; k++)
        acc = fmaf(e[k], f1w[k * 64 + j], acc);
    acc = fmaf(acc, gfc[j] * BN_RS, bfc[j]);
    z[j] = fmaxf(acc, 0.f);
    __syncthreads();
    if (j < 2) {
        float o = f2b[j];
        for (int k = 0; k < 64; k++)
            o = fmaf(z[k], f2w[k * 2 + j], o);
        out[g * 2 + j] = o;
    }
}

// ---------------- launch ----------------
extern "C" void kernel_launch(void* const* d_in, const int* in_sizes, int n_in,
                              void* d_out, int out_size) {
    const float* x   = (const float*)d_in[0];
    const int*   ei  = (const int*)  d_in[1];
    const float* ew  = (const float*)d_in[2];
    const float* W1  = (const float*)d_in[4];
    const float* b1  = (const float*)d_in[5];
    const float* g1  = (const float*)d_in[6];
    const float* bt1 = (const float*)d_in[7];
    const float* W2  = (const float*)d_in[8];
    const float* b2  = (const float*)d_in[9];
    const float* g2  = (const float*)d_in[10];
    const float* bt2 = (const float*)d_in[11];
    const float* pp  = (const float*)d_in[12];
    const float* W3  = (const float*)d_in[13];
    const float* b3  = (const float*)d_in[14];
    const float* g3  = (const float*)d_in[15];
    const float* bt3 = (const float*)d_in[16];
    const float* f1w = (const float*)d_in[17];
    const float* f1b = (const float*)d_in[18];
    const float* gfc = (const float*)d_in[19];
    const float* bfc = (const float*)d_in[20];
    const float* f2w = (const float*)d_in[21];
    const float* f2b = (const float*)d_in[22];
    float* out = (float*)d_out;

    const int* src = ei;
    const int* dst = ei + Etot;

    float *p_xw1, *p_h1, *p_xw2, *p_h2, *p_xw3, *p_h3;
    float *p_dis, *p_dis3, *p_score, *p_mask, *p_gate, *p_emb;
    __nv_bfloat16 *p_w1h, *p_w1l, *p_w2h, *p_w2l, *p_w3h, *p_w3l;
    cudaGetSymbolAddress((void**)&p_xw1,  g_xw1);
    cudaGetSymbolAddress((void**)&p_h1,   g_h1);
    cudaGetSymbolAddress((void**)&p_xw2,  g_xw2);
    cudaGetSymbolAddress((void**)&p_h2,   g_h2);
    cudaGetSymbolAddress((void**)&p_xw3,  g_xw3);
    cudaGetSymbolAddress((void**)&p_h3,   g_h3);
    cudaGetSymbolAddress((void**)&p_dis,  g_dis);
    cudaGetSymbolAddress((void**)&p_dis3, g_dis3);
    cudaGetSymbolAddress((void**)&p_score,g_score);
    cudaGetSymbolAddress((void**)&p_mask, g_mask);
    cudaGetSymbolAddress((void**)&p_gate, g_gate);
    cudaGetSymbolAddress((void**)&p_emb,  g_emb);
    cudaGetSymbolAddress((void**)&p_w1h,  g_w1h);
    cudaGetSymbolAddress((void**)&p_w1l,  g_w1l);
    cudaGetSymbolAddress((void**)&p_w2h,  g_w2h);
    cudaGetSymbolAddress((void**)&p_w2l,  g_w2l);
    cudaGetSymbolAddress((void**)&p_w3h,  g_w3h);
    cudaGetSymbolAddress((void**)&p_w3l,  g_w3l);

    constexpr int SM1 = wg_smem(64);
    constexpr int SM3 = wg_smem(128);
    cudaFuncSetAttribute((const void*)wgemm_kernel<64, 400, false>,
                         cudaFuncAttributeMaxDynamicSharedMemorySize, SM1);
    cudaFuncSetAttribute((const void*)wgemm_kernel<64, 64, false>,
                         cudaFuncAttributeMaxDynamicSharedMemorySize, SM1);
    cudaFuncSetAttribute((const void*)wgemm_kernel<128, 64, true>,
                         cudaFuncAttributeMaxDynamicSharedMemorySize, SM3);
    cudaFuncSetAttribute(agg_h64_kernel, cudaFuncAttributeMaxDynamicSharedMemorySize, SMEM_AGG64);
    cudaFuncSetAttribute(agg_h128_kernel,cudaFuncAttributeMaxDynamicSharedMemorySize, SMEM_AGG128);

    const int NB = Ntot / 256;
    const int EB = Etot / 256;

    // weight split (tiny)
    wconv_kernel<<<(448 * 64 + 255) / 256, 256>>>(W1, p_w1h, p_w1l, 400, 64, 448 * 64);
    wconv_kernel<<<16, 256>>>(W2, p_w2h, p_w2l, 64, 64, 64 * 64);
    wconv_kernel<<<32, 256>>>(W3, p_w3h, p_w3l, 64, 128, 64 * 128);

    // layer-1/2 symmetric normalization
    k_fill<<<NB, 256>>>(p_dis, 1.0f);
    k_accum_deg<<<EB, 256>>>(dst, ew, p_dis);
    k_fin_dis<<<NB, 256>>>(p_dis);

    // GCN1
    wgemm_kernel<64, 400, false><<<Ntot / 128, 256, SM1>>>(x, p_w1h, p_w1l, nullptr, p_xw1);
    agg_h64_kernel<<<Bg, 256, SMEM_AGG64>>>(p_xw1, p_dis, src, dst, ew, b1, g1, bt1, p_h1);

    // GCN2
    wgemm_kernel<64, 64, false><<<Ntot / 128, 256, SM1>>>(p_h1, p_w2h, p_w2l, nullptr, p_xw2);
    agg_h64_kernel<<<Bg, 256, SMEM_AGG64>>>(p_xw2, p_dis, src, dst, ew, b2, g2, bt2, p_h2);

    // TopK pooling
    score_kernel<<<Ntot / 8, 256>>>(p_h2, pp, p_score);
    topk_kernel<<<Bg, 256>>>(p_score, p_mask, p_gate);

    // layer-3 normalization over surviving edges
    k_copy<<<NB, 256>>>(p_dis3, p_mask);
    k_accum_deg3<<<EB, 256>>>(src, dst, ew, p_mask, p_dis3);
    k_fin_dis3<<<NB, 256>>>(p_dis3);

    // GCN3 (rows gated by score*mask)
    wgemm_kernel<128, 64, true><<<Ntot / 128, 256, SM3>>>(p_h2, p_w3h, p_w3l, p_gate, p_xw3);
    agg_h128_kernel<<<Bg, 256, SMEM_AGG128>>>(p_xw3, p_dis3, p_mask, src, dst, ew,
                                              b3, g3, bt3, p_h3);

    // readout + head
    readout_kernel<<<Bg, 128>>>(p_h3, p_mask, p_emb);
    head_kernel<<<Bg, 64>>>(p_emb, f1w, f1b, gfc, bfc, f2w, f2b, out);
}

// round 8
// speedup vs baseline: 2.4137x; 1.0297x over previous
#include <cuda_runtime.h>
#include <cuda_bf16.h>
#include <mma.h>
#include <math.h>
#include <stdint.h>

using namespace nvcuda;

// ---------------- problem constants ----------------
constexpr int Bg   = 256;     // graphs
constexpr int NPG  = 400;     // nodes per graph
constexpr int Ntot = Bg * NPG;        // 102400
constexpr int EPG  = 8000;    // edges per graph
constexpr int Etot = Bg * EPG;        // 2048000
constexpr int CIN  = 400;
constexpr int H    = 64;
constexpr int H3   = 128;
constexpr int KEEP = 200;
#define BN_RS 0.99999500003749968f  /* rsqrt(1+1e-5) */

// ---------------- scratch (device globals; no allocation allowed) ----------------
__device__ float g_xw1[Ntot * H];
__device__ float g_h1 [Ntot * H];
__device__ float g_xw2[Ntot * H];
__device__ float g_h2 [Ntot * H];
__device__ float g_xw3[Ntot * H3];
__device__ float g_dis [Ntot];
__device__ float g_score[Ntot];
__device__ float g_mask[Ntot];
__device__ float g_gate[Ntot];
__device__ float g_emb[Bg * 4 * H];   // [B, 256]
// prebuilt per-graph CSR buckets (built by agg1, reused by agg2)
__device__ unsigned short g_ebsrc[Etot];
__device__ float g_ebw[Etot];
__device__ int   g_eoff[Ntot];        // inclusive per-graph-local offsets
// split bf16 weights, row-major [KPAD][CO]
__device__ __nv_bfloat16 g_w1h[448 * 64];
__device__ __nv_bfloat16 g_w1l[448 * 64];
__device__ __nv_bfloat16 g_w2h[64 * 64];
__device__ __nv_bfloat16 g_w2l[64 * 64];
__device__ __nv_bfloat16 g_w3h[64 * 128];
__device__ __nv_bfloat16 g_w3l[64 * 128];

__device__ __forceinline__ uint32_t pack_bf2(__nv_bfloat16 a, __nv_bfloat16 b) {
    __nv_bfloat162 t = __halves2bfloat162(a, b);
    return *reinterpret_cast<uint32_t*>(&t);
}

// ---------------- all-weights bf16 split (single launch) ----------------
// region 0: W1 400x64 -> 448x64 ; region 1: W2 64x64 ; region 2: W3 64x128
__global__ void wconv_all_kernel(const float* __restrict__ W1, const float* __restrict__ W2,
                                 const float* __restrict__ W3,
                                 __nv_bfloat16* __restrict__ w1h, __nv_bfloat16* __restrict__ w1l,
                                 __nv_bfloat16* __restrict__ w2h, __nv_bfloat16* __restrict__ w2l,
                                 __nv_bfloat16* __restrict__ w3h, __nv_bfloat16* __restrict__ w3l) {
    int i = blockIdx.x * 256 + threadIdx.x;
    const float* W; __nv_bfloat16 *hi, *lo; int idx; int kdim, co;
    if (i < 448 * 64)            { W = W1; hi = w1h; lo = w1l; idx = i;             kdim = 400; co = 64; }
    else if (i < 448*64 + 64*64) { W = W2; hi = w2h; lo = w2l; idx = i - 448*64;    kdim = 64;  co = 64; }
    else if (i < 448*64 + 64*64 + 64*128)
                                 { W = W3; hi = w3h; lo = w3l; idx = i - 448*64 - 64*64; kdim = 64; co = 128; }
    else return;
    int k = idx / co;
    float v = (k < kdim) ? W[idx] : 0.f;
    __nv_bfloat16 h = __float2bfloat16(v);
    hi[idx] = h;
    lo[idx] = __float2bfloat16(v - __bfloat162float(h));
}

// ---------------- wmma bf16x3 GEMM: out[M,CO] = X[M,KDIM] @ W[KDIM,CO] ----------------
template<int CO, int KDIM, bool SCALE>
__global__ void __launch_bounds__(256) wgemm_kernel(
        const float* __restrict__ X,
        const __nv_bfloat16* __restrict__ wh,
        const __nv_bfloat16* __restrict__ wl,
        const float* __restrict__ rowscale,
        float* __restrict__ out) {
    constexpr int KCH = (KDIM + 63) / 64;
    constexpr int LDA = 72;
    constexpr int LDB = CO + 8;
    constexpr int NT  = CO / 16;

    extern __shared__ char smraw[];
    __nv_bfloat16* Ah = (__nv_bfloat16*)smraw;      // 128*LDA
    __nv_bfloat16* Al = Ah + 128 * LDA;
    __nv_bfloat16* Bh = Al + 128 * LDA;             // 64*LDB
    __nv_bfloat16* Bl = Bh + 64 * LDB;
    float* sOut = (float*)smraw;                    // union: 128*LDB floats

    const int tid  = threadIdx.x;
    const int warp = tid >> 5;
    const int rb   = blockIdx.x * 128;

    wmma::fragment<wmma::accumulator, 16, 16, 16, float> acc[NT];
    #pragma unroll
    for (int t = 0; t < NT; t++) wmma::fill_fragment(acc[t], 0.f);

    for (int ch = 0; ch < KCH; ch++) {
        const int kb = ch * 64;
        __syncthreads();
        // A chunk: 128x64 fp32 -> bf16 hi/lo
        #pragma unroll 2
        for (int i = tid * 4; i < 128 * 64; i += 1024) {
            int r = i >> 6, c = i & 63;
            float4 v = make_float4(0.f, 0.f, 0.f, 0.f);
            if ((KDIM & 63) == 0 || kb + c < KDIM)
                v = *(const float4*)&X[(size_t)(rb + r) * KDIM + kb + c];
            __nv_bfloat16 h0 = __float2bfloat16(v.x);
            __nv_bfloat16 h1 = __float2bfloat16(v.y);
            __nv_bfloat16 h2 = __float2bfloat16(v.z);
            __nv_bfloat16 h3 = __float2bfloat16(v.w);
            __nv_bfloat16 l0 = __float2bfloat16(v.x - __bfloat162float(h0));
            __nv_bfloat16 l1 = __float2bfloat16(v.y - __bfloat162float(h1));
            __nv_bfloat16 l2 = __float2bfloat16(v.z - __bfloat162float(h2));
            __nv_bfloat16 l3 = __float2bfloat16(v.w - __bfloat162float(h3));
            *(uint2*)&Ah[r * LDA + c] = make_uint2(pack_bf2(h0, h1), pack_bf2(h2, h3));
            *(uint2*)&Al[r * LDA + c] = make_uint2(pack_bf2(l0, l1), pack_bf2(l2, l3));
        }
        // B chunk: 64 x CO bf16 (pre-split)
        #pragma unroll 2
        for (int i = tid * 4; i < 64 * CO; i += 1024) {
            int r = i / CO, c = i & (CO - 1);
            *(uint2*)&Bh[r * LDB + c] = *(const uint2*)&wh[(size_t)(kb + r) * CO + c];
            *(uint2*)&Bl[r * LDB + c] = *(const uint2*)&wl[(size_t)(kb + r) * CO + c];
        }
        __syncthreads();

        const __nv_bfloat16* arow_h = Ah + (warp * 16) * LDA;
        const __nv_bfloat16* arow_l = Al + (warp * 16) * LDA;
        #pragma unroll
        for (int k16 = 0; k16 < 4; k16++) {
            wmma::fragment<wmma::matrix_a, 16, 16, 16, __nv_bfloat16, wmma::row_major> fa_h, fa_l;
            wmma::load_matrix_sync(fa_h, arow_h + k16 * 16, LDA);
            wmma::load_matrix_sync(fa_l, arow_l + k16 * 16, LDA);
            #pragma unroll
            for (int t = 0; t < NT; t++) {
                wmma::fragment<wmma::matrix_b, 16, 16, 16, __nv_bfloat16, wmma::row_major> fb_h, fb_l;
                wmma::load_matrix_sync(fb_h, Bh + (k16 * 16) * LDB + t * 16, LDB);
                wmma::load_matrix_sync(fb_l, Bl + (k16 * 16) * LDB + t * 16, LDB);
                wmma::mma_sync(acc[t], fa_h, fb_h, acc[t]);
                wmma::mma_sync(acc[t], fa_h, fb_l, acc[t]);
                wmma::mma_sync(acc[t], fa_l, fb_h, acc[t]);
            }
        }
    }
    __syncthreads();
    #pragma unroll
    for (int t = 0; t < NT; t++)
        wmma::store_matrix_sync(sOut + (warp * 16) * LDB + t * 16, acc[t], LDB,
                                wmma::mem_row_major);
    __syncthreads();
    #pragma unroll 2
    for (int i = tid * 4; i < 128 * CO; i += 1024) {
        int r = i / CO, c = i & (CO - 1);
        float4 v = *(float4*)&sOut[r * LDB + c];
        float rs = 1.f;
        if (SCALE) rs = rowscale[rb + r];
        v.x *= rs; v.y *= rs; v.z *= rs; v.w *= rs;
        *(float4*)&out[(size_t)(rb + r) * CO + c] = v;
    }
}

constexpr int wg_smem(int CO) {
    int lda = 72, ldb = CO + 8;
    int ab = (2 * 128 * lda + 2 * 64 * ldb) * 2;
    int os = 128 * ldb * 4;
    return ab > os ? ab : os;
}

// ======================================================================
// agg1: fused degree/dis + CSR build + store + gather + bias/BN/ReLU
// smem: ysm[400*64] dsm[400] cn[400] sc[512] bsrc[8000]u16 bw[8000]f32
// ======================================================================
constexpr int SMEM_AGG64 = (NPG*H + NPG)*4 + (NPG + 512)*4 + EPG*2 + EPG*4;

__global__ void agg1_kernel(const float* __restrict__ xw,
                            const int* __restrict__ src, const int* __restrict__ dstp,
                            const float* __restrict__ ew,
                            const float* __restrict__ bias, const float* __restrict__ gam,
                            const float* __restrict__ bet, float* __restrict__ out,
                            float* __restrict__ dis_out,
                            unsigned short* __restrict__ ebsrc_out,
                            float* __restrict__ ebw_out, int* __restrict__ eoff_out) {
    extern __shared__ float smf[];
    float* ysm = smf;
    float* dsm = ysm + NPG * H;
    int*   cn  = (int*)(dsm + NPG);
    int*   sc  = cn + NPG;
    unsigned short* bsrc = (unsigned short*)(sc + 512);
    float* bw  = (float*)(bsrc + EPG);

    const int g = blockIdx.x;
    const int nb = g * NPG;
    const int eb = g * EPG;
    const int tid = threadIdx.x;

    for (int i = tid; i < NPG; i += 256) { dsm[i] = 1.0f; cn[i] = 0; }  // self-loop weight 1
    __syncthreads();

    // pass 1: per-dst edge count + weighted degree
    for (int e = tid; e < EPG; e += 256) {
        int dl = dstp[eb + e] - nb;
        float w = ew[eb + e];
        atomicAdd(&cn[dl], 1);
        atomicAdd(&dsm[dl], w);
    }
    __syncthreads();
    for (int i = tid; i < NPG; i += 256) {
        float d = rsqrtf(dsm[i]);           // deg >= 1
        dsm[i] = d;
        dis_out[nb + i] = d;                // reused by agg2
    }
    __syncthreads();

    // ysm = dis * xW
    for (int i = tid * 4; i < NPG * H; i += 1024) {
        int node = i >> 6;
        float4 v = *(const float4*)&xw[(size_t)(nb + node) * H + (i & 63)];
        float d = dsm[node];
        v.x *= d; v.y *= d; v.z *= d; v.w *= d;
        *(float4*)&ysm[i] = v;
    }
    // inclusive scan of counts
    sc[tid] = cn[tid];
    sc[tid + 256] = (tid + 256 < NPG) ? cn[tid + 256] : 0;
    __syncthreads();
    for (int off = 1; off < 512; off <<= 1) {
        int a0 = sc[tid],       b0 = (tid >= off)       ? sc[tid - off]       : 0;
        int a1 = sc[tid + 256], b1 = (tid + 256 >= off) ? sc[tid + 256 - off] : 0;
        __syncthreads();
        sc[tid] = a0 + b0; sc[tid + 256] = a1 + b1;
        __syncthreads();
    }
    for (int i = tid; i < NPG; i += 256) { cn[i] = 0; eoff_out[nb + i] = sc[i]; }
    __syncthreads();

    // scatter edges into buckets
    for (int e = tid; e < EPG; e += 256) {
        int sl = src[eb + e] - nb;
        int dl = dstp[eb + e] - nb;
        int pos = (dl ? sc[dl - 1] : 0) + atomicAdd(&cn[dl], 1);
        bsrc[pos] = (unsigned short)sl;
        bw[pos]   = ew[eb + e];
    }
    __syncthreads();

    // persist buckets for agg2 (coalesced)
    for (int i = tid * 8; i < EPG; i += 2048)
        *(uint4*)&ebsrc_out[eb + i] = *(const uint4*)&bsrc[i];
    for (int i = tid * 4; i < EPG; i += 1024)
        *(float4*)&ebw_out[eb + i] = *(const float4*)&bw[i];

    // gather + epilogue
    const int lane = tid & 31;
    const int warp = tid >> 5;
    const float s0 = gam[lane] * BN_RS,      s1 = gam[lane + 32] * BN_RS;
    const float t0 = bet[lane],              t1 = bet[lane + 32];
    const float bb0 = bias[lane],            bb1 = bias[lane + 32];
    for (int dl = warp; dl < NPG; dl += 8) {
        int e0 = dl ? sc[dl - 1] : 0;
        int e1 = sc[dl];
        float a0 = ysm[dl * H + lane];
        float a1 = ysm[dl * H + lane + 32];
        for (int j = e0; j < e1; j++) {
            int sl = bsrc[j];
            float w = bw[j];
            a0 = fmaf(w, ysm[sl * H + lane],      a0);
            a1 = fmaf(w, ysm[sl * H + lane + 32], a1);
        }
        float d = dsm[dl];
        float v0 = fmaf(d, a0, bb0);
        float v1 = fmaf(d, a1, bb1);
        v0 = fmaxf(fmaf(v0, s0, t0), 0.f);
        v1 = fmaxf(fmaf(v1, s1, t1), 0.f);
        size_t o = (size_t)(nb + dl) * H;
        out[o + lane] = v0;
        out[o + lane + 32] = v1;
    }
}

// ======================================================================
// agg2: reuse prebuilt CSR + dis; gather + bias/BN/ReLU + fused score
// ======================================================================
__global__ void agg2_kernel(const float* __restrict__ xw, const float* __restrict__ dis,
                            const unsigned short* __restrict__ ebsrc,
                            const float* __restrict__ ebw, const int* __restrict__ eoff,
                            const float* __restrict__ ew_p,   // pool vector
                            const float* __restrict__ bias, const float* __restrict__ gam,
                            const float* __restrict__ bet, float* __restrict__ out,
                            float* __restrict__ score) {
    extern __shared__ float smf[];
    float* ysm = smf;
    float* dsm = ysm + NPG * H;
    int*   cn  = (int*)(dsm + NPG);       // unused (layout parity)
    int*   sc  = cn + NPG;
    unsigned short* bsrc = (unsigned short*)(sc + 512);
    float* bw  = (float*)(bsrc + EPG);

    const int g = blockIdx.x;
    const int nb = g * NPG;
    const int eb = g * EPG;
    const int tid = threadIdx.x;

    for (int i = tid; i < NPG; i += 256) {
        dsm[i] = dis[nb + i];
        sc[i]  = eoff[nb + i];
    }
    // load prebuilt buckets
    for (int i = tid * 8; i < EPG; i += 2048)
        *(uint4*)&bsrc[i] = *(const uint4*)&ebsrc[eb + i];
    for (int i = tid * 4; i < EPG; i += 1024)
        *(float4*)&bw[i] = *(const float4*)&ebw[eb + i];
    __syncthreads();

    for (int i = tid * 4; i < NPG * H; i += 1024) {
        int node = i >> 6;
        float4 v = *(const float4*)&xw[(size_t)(nb + node) * H + (i & 63)];
        float d = dsm[node];
        v.x *= d; v.y *= d; v.z *= d; v.w *= d;
        *(float4*)&ysm[i] = v;
    }
    __syncthreads();

    const int lane = tid & 31;
    const int warp = tid >> 5;
    const float s0 = gam[lane] * BN_RS,      s1 = gam[lane + 32] * BN_RS;
    const float t0 = bet[lane],              t1 = bet[lane + 32];
    const float bb0 = bias[lane],            bb1 = bias[lane + 32];
    // pool vector for fused score
    const float p0 = ew_p[lane], p1 = ew_p[lane + 32];
    float pn = p0 * p0 + p1 * p1;
    #pragma unroll
    for (int o = 16; o; o >>= 1) pn += __shfl_xor_sync(0xffffffffu, pn, o);
    const float ipn = rsqrtf(pn);

    for (int dl = warp; dl < NPG; dl += 8) {
        int e0 = dl ? sc[dl - 1] : 0;
        int e1 = sc[dl];
        float a0 = ysm[dl * H + lane];
        float a1 = ysm[dl * H + lane + 32];
        for (int j = e0; j < e1; j++) {
            int sl = bsrc[j];
            float w = bw[j];
            a0 = fmaf(w, ysm[sl * H + lane],      a0);
            a1 = fmaf(w, ysm[sl * H + lane + 32], a1);
        }
        float d = dsm[dl];
        float v0 = fmaf(d, a0, bb0);
        float v1 = fmaf(d, a1, bb1);
        v0 = fmaxf(fmaf(v0, s0, t0), 0.f);
        v1 = fmaxf(fmaf(v1, s1, t1), 0.f);
        size_t o = (size_t)(nb + dl) * H;
        out[o + lane] = v0;
        out[o + lane + 32] = v1;
        // fused pooling score
        float dsc = v0 * p0 + v1 * p1;
        #pragma unroll
        for (int of = 16; of; of >>= 1) dsc += __shfl_xor_sync(0xffffffffu, dsc, of);
        if (lane == 0) score[nb + dl] = tanhf(dsc * ipn);
    }
}

// ======================================================================
// agg3: fused dis3 + masked CSR + gather + bias/BN/ReLU + mean/max readout
// ======================================================================
constexpr int SMEM_AGG3 = (NPG*H + 2*NPG)*4 + (NPG + 512)*4 + EPG*2 + EPG*4 + 2 * 8 * 64 * 4;

__global__ void agg3_kernel(const float* __restrict__ xw,
                            const float* __restrict__ mask,
                            const int* __restrict__ src, const int* __restrict__ dstp,
                            const float* __restrict__ ew,
                            const float* __restrict__ bias, const float* __restrict__ gam,
                            const float* __restrict__ bet, float* __restrict__ emb) {
    extern __shared__ float smf[];
    float* ysm = smf;
    float* dsm = ysm + NPG * H;
    float* msm = dsm + NPG;
    int*   cn  = (int*)(msm + NPG);
    int*   sc  = cn + NPG;
    unsigned short* bsrc = (unsigned short*)(sc + 512);
    float* bw   = (float*)(bsrc + EPG);
    float* psum = bw + EPG;              // [8][64]
    float* pmax = psum + 8 * 64;         // [8][64]

    const int g = blockIdx.x;
    const int nb = g * NPG;
    const int eb = g * EPG;
    const int tid = threadIdx.x;

    for (int i = tid; i < NPG; i += 256) {
        float m = mask[nb + i];
        msm[i] = m;
        dsm[i] = m;          // degree init = self-loop weight (mask)
        cn[i] = 0;
    }
    __syncthreads();

    // pass 1: masked count + weighted degree
    for (int e = tid; e < EPG; e += 256) {
        int sl = src[eb + e] - nb;
        int dl = dstp[eb + e] - nb;
        if (msm[sl] != 0.f && msm[dl] != 0.f) {
            atomicAdd(&cn[dl], 1);
            atomicAdd(&dsm[dl], ew[eb + e]);
        }
    }
    __syncthreads();
    for (int i = tid; i < NPG; i += 256) {
        float v = dsm[i];
        dsm[i] = (v > 0.f) ? rsqrtf(fmaxf(v, 1e-12f)) : 0.f;
    }
    __syncthreads();

    sc[tid] = cn[tid];
    sc[tid + 256] = (tid + 256 < NPG) ? cn[tid + 256] : 0;
    __syncthreads();
    for (int off = 1; off < 512; off <<= 1) {
        int a0 = sc[tid],       b0 = (tid >= off)       ? sc[tid - off]       : 0;
        int a1 = sc[tid + 256], b1 = (tid + 256 >= off) ? sc[tid + 256 - off] : 0;
        __syncthreads();
        sc[tid] = a0 + b0; sc[tid + 256] = a1 + b1;
        __syncthreads();
    }
    for (int i = tid; i < NPG; i += 256) cn[i] = 0;
    __syncthreads();
    for (int e = tid; e < EPG; e += 256) {
        int sl = src[eb + e] - nb;
        int dl = dstp[eb + e] - nb;
        if (msm[sl] != 0.f && msm[dl] != 0.f) {
            int pos = (dl ? sc[dl - 1] : 0) + atomicAdd(&cn[dl], 1);
            bsrc[pos] = (unsigned short)sl;
            bw[pos]   = ew[eb + e];
        }
    }

    const int lane = tid & 31;
    const int warp = tid >> 5;
    #pragma unroll
    for (int hf = 0; hf < 2; hf++) {
        __syncthreads();
        for (int i = tid * 4; i < NPG * H; i += 1024) {
            int node = i >> 6;
            float4 v = *(const float4*)&xw[(size_t)(nb + node) * H3 + hf * H + (i & 63)];
            float d = dsm[node];
            v.x *= d; v.y *= d; v.z *= d; v.w *= d;
            *(float4*)&ysm[i] = v;
        }
        __syncthreads();
        const int f0 = hf * H + lane, f1 = hf * H + lane + 32;
        const float s0 = gam[f0] * BN_RS, s1 = gam[f1] * BN_RS;
        const float t0 = bet[f0],         t1 = bet[f1];
        const float bb0 = bias[f0],       bb1 = bias[f1];
        float sum0 = 0.f, sum1 = 0.f, mx0 = -INFINITY, mx1 = -INFINITY;
        for (int dl = warp; dl < NPG; dl += 8) {
            if (msm[dl] == 0.f) continue;          // dropped nodes never contribute
            int e0 = dl ? sc[dl - 1] : 0;
            int e1 = sc[dl];
            float a0 = ysm[dl * H + lane];          // mask==1 on kept nodes
            float a1 = ysm[dl * H + lane + 32];
            for (int j = e0; j < e1; j++) {
                int sl = bsrc[j];
                float w = bw[j];
                a0 = fmaf(w, ysm[sl * H + lane],      a0);
                a1 = fmaf(w, ysm[sl * H + lane + 32], a1);
            }
            float d = dsm[dl];
            float v0 = fmaf(d, a0, bb0);
            float v1 = fmaf(d, a1, bb1);
            v0 = fmaxf(fmaf(v0, s0, t0), 0.f);
            v1 = fmaxf(fmaf(v1, s1, t1), 0.f);
            sum0 += v0; sum1 += v1;
            mx0 = fmaxf(mx0, v0); mx1 = fmaxf(mx1, v1);
        }
        psum[warp * 64 + lane]      = sum0;
        psum[warp * 64 + lane + 32] = sum1;
        pmax[warp * 64 + lane]      = mx0;
        pmax[warp * 64 + lane + 32] = mx1;
        __syncthreads();
        if (tid < 64) {   // deterministic fixed-order combine
            float s = 0.f, m = -INFINITY;
            #pragma unroll
            for (int w = 0; w < 8; w++) {
                s += psum[w * 64 + tid];
                m = fmaxf(m, pmax[w * 64 + tid]);
            }
            emb[g * 256 + hf * 64 + tid]       = s * (1.f / KEEP);
            emb[g * 256 + 128 + hf * 64 + tid] = m;
        }
    }
}

// ---------------- top-k (200 of 400) per graph ----------------
__global__ void topk_kernel(const float* __restrict__ score, float* __restrict__ mask,
                            float* __restrict__ gate) {
    __shared__ float s[512];
    __shared__ float orig[NPG];
    __shared__ unsigned char km[NPG];
    __shared__ int cnt;
    const int g = blockIdx.x, tid = threadIdx.x;
    for (int i = tid; i < 512; i += 256) {
        float v = (i < NPG) ? score[g * NPG + i] : -INFINITY;
        s[i] = v;
        if (i < NPG) orig[i] = v;
    }
    if (tid == 0) cnt = 0;
    __syncthreads();
    for (int k = 2; k <= 512; k <<= 1) {
        for (int j = k >> 1; j > 0; j >>= 1) {
            for (int t = tid; t < 512; t += 256) {
                int ixj = t ^ j;
                if (ixj > t) {
                    float a = s[t], b = s[ixj];
                    bool sw = ((t & k) == 0) ? (a > b) : (a < b);
                    if (sw) { s[t] = b; s[ixj] = a; }
                }
            }
            __syncthreads();
        }
    }
    float thr = s[512 - KEEP];
    int local = 0;
    for (int i = tid; i < NPG; i += 256)
        if (orig[i] > thr) local++;
    atomicAdd(&cnt, local);
    __syncthreads();
    if (tid == 0) {
        int rem = KEEP - cnt;
        for (int i = 0; i < NPG; i++) {
            unsigned char m = (orig[i] > thr) ? 1 : 0;
            if (!m && orig[i] == thr && rem > 0) { m = 1; rem--; }
            km[i] = m;
        }
    }
    __syncthreads();
    for (int i = tid; i < NPG; i += 256) {
        float m = km[i] ? 1.f : 0.f;
        mask[g * NPG + i] = m;
        gate[g * NPG + i] = m * orig[i];
    }
}

// ---------------- MLP head ----------------
__global__ void head_kernel(const float* __restrict__ emb,
                            const float* __restrict__ f1w, const float* __restrict__ f1b,
                            const float* __restrict__ gfc, const float* __restrict__ bfc,
                            const float* __restrict__ f2w, const float* __restrict__ f2b,
                            float* __restrict__ out) {
    __shared__ float z[64];
    const int g = blockIdx.x, j = threadIdx.x;
    float acc = f1b[j];
    const float* e = &emb[g * 256];
    #pragma unroll 8
    for (int k = 0; k < 256; k++)
        acc = fmaf(e[k], f1w[k * 64 + j], acc);
    acc = fmaf(acc, gfc[j] * BN_RS, bfc[j]);
    z[j] = fmaxf(acc, 0.f);
    __syncthreads();
    if (j < 2) {
        float o = f2b[j];
        for (int k = 0; k < 64; k++)
            o = fmaf(z[k], f2w[k * 2 + j], o);
        out[g * 2 + j] = o;
    }
}

// ---------------- launch ----------------
extern "C" void kernel_launch(void* const* d_in, const int* in_sizes, int n_in,
                              void* d_out, int out_size) {
    const float* x   = (const float*)d_in[0];
    const int*   ei  = (const int*)  d_in[1];
    const float* ew  = (const float*)d_in[2];
    const float* W1  = (const float*)d_in[4];
    const float* b1  = (const float*)d_in[5];
    const float* g1  = (const float*)d_in[6];
    const float* bt1 = (const float*)d_in[7];
    const float* W2  = (const float*)d_in[8];
    const float* b2  = (const float*)d_in[9];
    const float* g2  = (const float*)d_in[10];
    const float* bt2 = (const float*)d_in[11];
    const float* pp  = (const float*)d_in[12];
    const float* W3  = (const float*)d_in[13];
    const float* b3  = (const float*)d_in[14];
    const float* g3  = (const float*)d_in[15];
    const float* bt3 = (const float*)d_in[16];
    const float* f1w = (const float*)d_in[17];
    const float* f1b = (const float*)d_in[18];
    const float* gfc = (const float*)d_in[19];
    const float* bfc = (const float*)d_in[20];
    const float* f2w = (const float*)d_in[21];
    const float* f2b = (const float*)d_in[22];
    float* out = (float*)d_out;

    const int* src = ei;
    const int* dst = ei + Etot;

    float *p_xw1, *p_h1, *p_xw2, *p_h2, *p_xw3;
    float *p_dis, *p_score, *p_mask, *p_gate, *p_emb, *p_ebw;
    unsigned short* p_ebsrc;
    int* p_eoff;
    __nv_bfloat16 *p_w1h, *p_w1l, *p_w2h, *p_w2l, *p_w3h, *p_w3l;
    cudaGetSymbolAddress((void**)&p_xw1,  g_xw1);
    cudaGetSymbolAddress((void**)&p_h1,   g_h1);
    cudaGetSymbolAddress((void**)&p_xw2,  g_xw2);
    cudaGetSymbolAddress((void**)&p_h2,   g_h2);
    cudaGetSymbolAddress((void**)&p_xw3,  g_xw3);
    cudaGetSymbolAddress((void**)&p_dis,  g_dis);
    cudaGetSymbolAddress((void**)&p_score,g_score);
    cudaGetSymbolAddress((void**)&p_mask, g_mask);
    cudaGetSymbolAddress((void**)&p_gate, g_gate);
    cudaGetSymbolAddress((void**)&p_emb,  g_emb);
    cudaGetSymbolAddress((void**)&p_ebsrc,g_ebsrc);
    cudaGetSymbolAddress((void**)&p_ebw,  g_ebw);
    cudaGetSymbolAddress((void**)&p_eoff, g_eoff);
    cudaGetSymbolAddress((void**)&p_w1h,  g_w1h);
    cudaGetSymbolAddress((void**)&p_w1l,  g_w1l);
    cudaGetSymbolAddress((void**)&p_w2h,  g_w2h);
    cudaGetSymbolAddress((void**)&p_w2l,  g_w2l);
    cudaGetSymbolAddress((void**)&p_w3h,  g_w3h);
    cudaGetSymbolAddress((void**)&p_w3l,  g_w3l);

    constexpr int SM1 = wg_smem(64);
    constexpr int SM3 = wg_smem(128);
    cudaFuncSetAttribute((const void*)wgemm_kernel<64, 400, false>,
                         cudaFuncAttributeMaxDynamicSharedMemorySize, SM1);
    cudaFuncSetAttribute((const void*)wgemm_kernel<64, 64, false>,
                         cudaFuncAttributeMaxDynamicSharedMemorySize, SM1);
    cudaFuncSetAttribute((const void*)wgemm_kernel<128, 64, true>,
                         cudaFuncAttributeMaxDynamicSharedMemorySize, SM3);
    cudaFuncSetAttribute(agg1_kernel, cudaFuncAttributeMaxDynamicSharedMemorySize, SMEM_AGG64);
    cudaFuncSetAttribute(agg2_kernel, cudaFuncAttributeMaxDynamicSharedMemorySize, SMEM_AGG64);
    cudaFuncSetAttribute(agg3_kernel, cudaFuncAttributeMaxDynamicSharedMemorySize, SMEM_AGG3);

    // 0: weight split (single launch)
    wconv_all_kernel<<<(448*64 + 64*64 + 64*128 + 255) / 256, 256>>>(
        W1, W2, W3, p_w1h, p_w1l, p_w2h, p_w2l, p_w3h, p_w3l);

    // 1: GCN1 GEMM
    wgemm_kernel<64, 400, false><<<Ntot / 128, 256, SM1>>>(x, p_w1h, p_w1l, nullptr, p_xw1);
    // 2: GCN1 aggregation (fused degree + CSR build/persist)
    agg1_kernel<<<Bg, 256, SMEM_AGG64>>>(p_xw1, src, dst, ew, b1, g1, bt1, p_h1,
                                         p_dis, p_ebsrc, p_ebw, p_eoff);
    // 3: GCN2 GEMM
    wgemm_kernel<64, 64, false><<<Ntot / 128, 256, SM1>>>(p_h1, p_w2h, p_w2l, nullptr, p_xw2);
    // 4: GCN2 aggregation (reused CSR, fused score)
    agg2_kernel<<<Bg, 256, SMEM_AGG64>>>(p_xw2, p_dis, p_ebsrc, p_ebw, p_eoff, pp,
                                         b2, g2, bt2, p_h2, p_score);
    // 5: TopK
    topk_kernel<<<Bg, 256>>>(p_score, p_mask, p_gate);
    // 6: GCN3 GEMM (rows gated by score*mask)
    wgemm_kernel<128, 64, true><<<Ntot / 128, 256, SM3>>>(p_h2, p_w3h, p_w3l, p_gate, p_xw3);
    // 7: GCN3 aggregation (fused dis3 + masked CSR + readout)
    agg3_kernel<<<Bg, 256, SMEM_AGG3>>>(p_xw3, p_mask, src, dst, ew, b3, g3, bt3, p_emb);
    // 8: head
    head_kernel<<<Bg, 64>>>(p_emb, f1w, f1b, gfc, bfc, f2w, f2b, out);
}

// round 9
// speedup vs baseline: 3.0494x; 1.2634x over previous
#include <cuda_runtime.h>
#include <cuda_bf16.h>
#include <mma.h>
#include <math.h>
#include <stdint.h>

using namespace nvcuda;

// ---------------- problem constants ----------------
constexpr int Bg   = 256;     // graphs
constexpr int NPG  = 400;     // nodes per graph
constexpr int Ntot = Bg * NPG;        // 102400
constexpr int EPG  = 8000;    // edges per graph
constexpr int Etot = Bg * EPG;        // 2048000
constexpr int CIN  = 400;
constexpr int H    = 64;
constexpr int H3   = 128;
constexpr int KEEP = 200;
constexpr int AT   = 512;     // agg kernel threads
constexpr int AW   = AT / 32; // 16 warps
#define BN_RS 0.99999500003749968f  /* rsqrt(1+1e-5) */

// ---------------- scratch (device globals; no allocation allowed) ----------------
__device__ float g_xw1[Ntot * H];
__device__ float g_h1 [Ntot * H];
__device__ float g_xw2[Ntot * H];
__device__ float g_h2 [Ntot * H];
__device__ float g_xw3[Ntot * H3];
__device__ float g_dis [Ntot];
__device__ float g_score[Ntot];
__device__ float g_mask[Ntot];
__device__ float g_gate[Ntot];
__device__ float g_emb[Bg * 4 * H];   // [B, 256]
// prebuilt per-graph CSR buckets (built by agg1, reused by agg2)
__device__ unsigned short g_ebsrc[Etot];
__device__ float g_ebw[Etot];
__device__ int   g_eoff[Ntot];        // inclusive per-graph-local offsets
// split bf16 weights, row-major [KPAD][CO]
__device__ __nv_bfloat16 g_w1h[448 * 64];
__device__ __nv_bfloat16 g_w1l[448 * 64];
__device__ __nv_bfloat16 g_w2h[64 * 64];
__device__ __nv_bfloat16 g_w2l[64 * 64];
__device__ __nv_bfloat16 g_w3h[64 * 128];
__device__ __nv_bfloat16 g_w3l[64 * 128];

__device__ __forceinline__ uint32_t pack_bf2(__nv_bfloat16 a, __nv_bfloat16 b) {
    __nv_bfloat162 t = __halves2bfloat162(a, b);
    return *reinterpret_cast<uint32_t*>(&t);
}

// ---------------- all-weights bf16 split (single launch) ----------------
__global__ void wconv_all_kernel(const float* __restrict__ W1, const float* __restrict__ W2,
                                 const float* __restrict__ W3,
                                 __nv_bfloat16* __restrict__ w1h, __nv_bfloat16* __restrict__ w1l,
                                 __nv_bfloat16* __restrict__ w2h, __nv_bfloat16* __restrict__ w2l,
                                 __nv_bfloat16* __restrict__ w3h, __nv_bfloat16* __restrict__ w3l) {
    int i = blockIdx.x * 256 + threadIdx.x;
    const float* W; __nv_bfloat16 *hi, *lo; int idx; int kdim, co;
    if (i < 448 * 64)            { W = W1; hi = w1h; lo = w1l; idx = i;             kdim = 400; co = 64; }
    else if (i < 448*64 + 64*64) { W = W2; hi = w2h; lo = w2l; idx = i - 448*64;    kdim = 64;  co = 64; }
    else if (i < 448*64 + 64*64 + 64*128)
                                 { W = W3; hi = w3h; lo = w3l; idx = i - 448*64 - 64*64; kdim = 64; co = 128; }
    else return;
    int k = idx / co;
    float v = (k < kdim) ? W[idx] : 0.f;
    __nv_bfloat16 h = __float2bfloat16(v);
    hi[idx] = h;
    lo[idx] = __float2bfloat16(v - __bfloat162float(h));
}

// ---------------- wmma bf16x3 GEMM: out[M,CO] = X[M,KDIM] @ W[KDIM,CO] ----------------
template<int CO, int KDIM, bool SCALE>
__global__ void __launch_bounds__(256) wgemm_kernel(
        const float* __restrict__ X,
        const __nv_bfloat16* __restrict__ wh,
        const __nv_bfloat16* __restrict__ wl,
        const float* __restrict__ rowscale,
        float* __restrict__ out) {
    constexpr int KCH = (KDIM + 63) / 64;
    constexpr int LDA = 72;
    constexpr int LDB = CO + 8;
    constexpr int NT  = CO / 16;

    extern __shared__ char smraw[];
    __nv_bfloat16* Ah = (__nv_bfloat16*)smraw;      // 128*LDA
    __nv_bfloat16* Al = Ah + 128 * LDA;
    __nv_bfloat16* Bh = Al + 128 * LDA;             // 64*LDB
    __nv_bfloat16* Bl = Bh + 64 * LDB;
    float* sOut = (float*)smraw;                    // union: 128*LDB floats

    const int tid  = threadIdx.x;
    const int warp = tid >> 5;
    const int rb   = blockIdx.x * 128;

    wmma::fragment<wmma::accumulator, 16, 16, 16, float> acc[NT];
    #pragma unroll
    for (int t = 0; t < NT; t++) wmma::fill_fragment(acc[t], 0.f);

    for (int ch = 0; ch < KCH; ch++) {
        const int kb = ch * 64;
        __syncthreads();
        // A chunk: 128x64 fp32 -> bf16 hi/lo
        #pragma unroll 2
        for (int i = tid * 4; i < 128 * 64; i += 1024) {
            int r = i >> 6, c = i & 63;
            float4 v = make_float4(0.f, 0.f, 0.f, 0.f);
            if ((KDIM & 63) == 0 || kb + c < KDIM)
                v = *(const float4*)&X[(size_t)(rb + r) * KDIM + kb + c];
            __nv_bfloat16 h0 = __float2bfloat16(v.x);
            __nv_bfloat16 h1 = __float2bfloat16(v.y);
            __nv_bfloat16 h2 = __float2bfloat16(v.z);
            __nv_bfloat16 h3 = __float2bfloat16(v.w);
            __nv_bfloat16 l0 = __float2bfloat16(v.x - __bfloat162float(h0));
            __nv_bfloat16 l1 = __float2bfloat16(v.y - __bfloat162float(h1));
            __nv_bfloat16 l2 = __float2bfloat16(v.z - __bfloat162float(h2));
            __nv_bfloat16 l3 = __float2bfloat16(v.w - __bfloat162float(h3));
            *(uint2*)&Ah[r * LDA + c] = make_uint2(pack_bf2(h0, h1), pack_bf2(h2, h3));
            *(uint2*)&Al[r * LDA + c] = make_uint2(pack_bf2(l0, l1), pack_bf2(l2, l3));
        }
        // B chunk: 64 x CO bf16 (pre-split)
        #pragma unroll 2
        for (int i = tid * 4; i < 64 * CO; i += 1024) {
            int r = i / CO, c = i & (CO - 1);
            *(uint2*)&Bh[r * LDB + c] = *(const uint2*)&wh[(size_t)(kb + r) * CO + c];
            *(uint2*)&Bl[r * LDB + c] = *(const uint2*)&wl[(size_t)(kb + r) * CO + c];
        }
        __syncthreads();

        const __nv_bfloat16* arow_h = Ah + (warp * 16) * LDA;
        const __nv_bfloat16* arow_l = Al + (warp * 16) * LDA;
        #pragma unroll
        for (int k16 = 0; k16 < 4; k16++) {
            wmma::fragment<wmma::matrix_a, 16, 16, 16, __nv_bfloat16, wmma::row_major> fa_h, fa_l;
            wmma::load_matrix_sync(fa_h, arow_h + k16 * 16, LDA);
            wmma::load_matrix_sync(fa_l, arow_l + k16 * 16, LDA);
            #pragma unroll
            for (int t = 0; t < NT; t++) {
                wmma::fragment<wmma::matrix_b, 16, 16, 16, __nv_bfloat16, wmma::row_major> fb_h, fb_l;
                wmma::load_matrix_sync(fb_h, Bh + (k16 * 16) * LDB + t * 16, LDB);
                wmma::load_matrix_sync(fb_l, Bl + (k16 * 16) * LDB + t * 16, LDB);
                wmma::mma_sync(acc[t], fa_h, fb_h, acc[t]);
                wmma::mma_sync(acc[t], fa_h, fb_l, acc[t]);
                wmma::mma_sync(acc[t], fa_l, fb_h, acc[t]);
            }
        }
    }
    __syncthreads();
    #pragma unroll
    for (int t = 0; t < NT; t++)
        wmma::store_matrix_sync(sOut + (warp * 16) * LDB + t * 16, acc[t], LDB,
                                wmma::mem_row_major);
    __syncthreads();
    #pragma unroll 2
    for (int i = tid * 4; i < 128 * CO; i += 1024) {
        int r = i / CO, c = i & (CO - 1);
        float4 v = *(float4*)&sOut[r * LDB + c];
        float rs = 1.f;
        if (SCALE) rs = rowscale[rb + r];
        v.x *= rs; v.y *= rs; v.z *= rs; v.w *= rs;
        *(float4*)&out[(size_t)(rb + r) * CO + c] = v;
    }
}

constexpr int wg_smem(int CO) {
    int lda = 72, ldb = CO + 8;
    int ab = (2 * 128 * lda + 2 * 64 * ldb) * 2;
    int os = 128 * ldb * 4;
    return ab > os ? ab : os;
}

// ---------------- shared gather helper: 4x-unrolled CSR edge accumulation ----------------
__device__ __forceinline__ void gather_row(const unsigned short* __restrict__ bsrc,
                                           const float* __restrict__ bw,
                                           const float* __restrict__ ysm,
                                           int e0, int e1, int lane,
                                           float& a0, float& a1) {
    int j = e0;
    for (; j + 4 <= e1; j += 4) {
        int s0 = bsrc[j], s1 = bsrc[j + 1], s2 = bsrc[j + 2], s3 = bsrc[j + 3];
        float w0 = bw[j], w1 = bw[j + 1], w2 = bw[j + 2], w3 = bw[j + 3];
        float y00 = ysm[s0 * H + lane],      y01 = ysm[s0 * H + lane + 32];
        float y10 = ysm[s1 * H + lane],      y11 = ysm[s1 * H + lane + 32];
        float y20 = ysm[s2 * H + lane],      y21 = ysm[s2 * H + lane + 32];
        float y30 = ysm[s3 * H + lane],      y31 = ysm[s3 * H + lane + 32];
        a0 = fmaf(w0, y00, a0); a1 = fmaf(w0, y01, a1);
        a0 = fmaf(w1, y10, a0); a1 = fmaf(w1, y11, a1);
        a0 = fmaf(w2, y20, a0); a1 = fmaf(w2, y21, a1);
        a0 = fmaf(w3, y30, a0); a1 = fmaf(w3, y31, a1);
    }
    for (; j < e1; j++) {
        int sl = bsrc[j];
        float w = bw[j];
        a0 = fmaf(w, ysm[sl * H + lane],      a0);
        a1 = fmaf(w, ysm[sl * H + lane + 32], a1);
    }
}

// ======================================================================
// agg1: fused degree/dis + CSR build + store + gather + bias/BN/ReLU
// smem: ysm[400*64] dsm[400] cn[400] sc[512] bsrc[8000]u16 bw[8000]f32
// ======================================================================
constexpr int SMEM_AGG64 = (NPG*H + NPG)*4 + (NPG + 512)*4 + EPG*2 + EPG*4;

__global__ void __launch_bounds__(AT) agg1_kernel(
                            const float* __restrict__ xw,
                            const int* __restrict__ src, const int* __restrict__ dstp,
                            const float* __restrict__ ew,
                            const float* __restrict__ bias, const float* __restrict__ gam,
                            const float* __restrict__ bet, float* __restrict__ out,
                            float* __restrict__ dis_out,
                            unsigned short* __restrict__ ebsrc_out,
                            float* __restrict__ ebw_out, int* __restrict__ eoff_out) {
    extern __shared__ float smf[];
    float* ysm = smf;
    float* dsm = ysm + NPG * H;
    int*   cn  = (int*)(dsm + NPG);
    int*   sc  = cn + NPG;
    unsigned short* bsrc = (unsigned short*)(sc + 512);
    float* bw  = (float*)(bsrc + EPG);

    const int g = blockIdx.x;
    const int nb = g * NPG;
    const int eb = g * EPG;
    const int tid = threadIdx.x;

    for (int i = tid; i < NPG; i += AT) { dsm[i] = 1.0f; cn[i] = 0; }
    __syncthreads();

    // pass 1: per-dst edge count + weighted degree
    for (int e = tid; e < EPG; e += AT) {
        int dl = dstp[eb + e] - nb;
        float w = ew[eb + e];
        atomicAdd(&cn[dl], 1);
        atomicAdd(&dsm[dl], w);
    }
    __syncthreads();
    for (int i = tid; i < NPG; i += AT) {
        float d = rsqrtf(dsm[i]);           // deg >= 1
        dsm[i] = d;
        dis_out[nb + i] = d;
    }
    __syncthreads();

    // ysm = dis * xW
    for (int i = tid * 4; i < NPG * H; i += AT * 4) {
        int node = i >> 6;
        float4 v = *(const float4*)&xw[(size_t)(nb + node) * H + (i & 63)];
        float d = dsm[node];
        v.x *= d; v.y *= d; v.z *= d; v.w *= d;
        *(float4*)&ysm[i] = v;
    }
    // inclusive scan of counts (512 threads, 512 elems)
    sc[tid] = (tid < NPG) ? cn[tid] : 0;
    __syncthreads();
    #pragma unroll
    for (int off = 1; off < 512; off <<= 1) {
        int v = sc[tid];
        int a = (tid >= off) ? sc[tid - off] : 0;
        __syncthreads();
        sc[tid] = v + a;
        __syncthreads();
    }
    for (int i = tid; i < NPG; i += AT) { cn[i] = 0; eoff_out[nb + i] = sc[i]; }
    __syncthreads();

    // scatter edges into buckets
    for (int e = tid; e < EPG; e += AT) {
        int sl = src[eb + e] - nb;
        int dl = dstp[eb + e] - nb;
        int pos = (dl ? sc[dl - 1] : 0) + atomicAdd(&cn[dl], 1);
        bsrc[pos] = (unsigned short)sl;
        bw[pos]   = ew[eb + e];
    }
    __syncthreads();

    // persist buckets for agg2 (coalesced)
    for (int i = tid * 8; i < EPG; i += AT * 8)
        *(uint4*)&ebsrc_out[eb + i] = *(const uint4*)&bsrc[i];
    for (int i = tid * 4; i < EPG; i += AT * 4)
        *(float4*)&ebw_out[eb + i] = *(const float4*)&bw[i];

    // gather + epilogue
    const int lane = tid & 31;
    const int warp = tid >> 5;
    const float s0 = gam[lane] * BN_RS,      s1 = gam[lane + 32] * BN_RS;
    const float t0 = bet[lane],              t1 = bet[lane + 32];
    const float bb0 = bias[lane],            bb1 = bias[lane + 32];
    for (int dl = warp; dl < NPG; dl += AW) {
        int e0 = dl ? sc[dl - 1] : 0;
        int e1 = sc[dl];
        float a0 = ysm[dl * H + lane];
        float a1 = ysm[dl * H + lane + 32];
        gather_row(bsrc, bw, ysm, e0, e1, lane, a0, a1);
        float d = dsm[dl];
        float v0 = fmaf(d, a0, bb0);
        float v1 = fmaf(d, a1, bb1);
        v0 = fmaxf(fmaf(v0, s0, t0), 0.f);
        v1 = fmaxf(fmaf(v1, s1, t1), 0.f);
        size_t o = (size_t)(nb + dl) * H;
        out[o + lane] = v0;
        out[o + lane + 32] = v1;
    }
}

// ======================================================================
// agg2: reuse prebuilt CSR + dis; gather + bias/BN/ReLU + fused score
// ======================================================================
__global__ void __launch_bounds__(AT) agg2_kernel(
                            const float* __restrict__ xw, const float* __restrict__ dis,
                            const unsigned short* __restrict__ ebsrc,
                            const float* __restrict__ ebw, const int* __restrict__ eoff,
                            const float* __restrict__ ew_p,   // pool vector
                            const float* __restrict__ bias, const float* __restrict__ gam,
                            const float* __restrict__ bet, float* __restrict__ out,
                            float* __restrict__ score) {
    extern __shared__ float smf[];
    float* ysm = smf;
    float* dsm = ysm + NPG * H;
    int*   cn  = (int*)(dsm + NPG);       // layout parity
    int*   sc  = cn + NPG;
    unsigned short* bsrc = (unsigned short*)(sc + 512);
    float* bw  = (float*)(bsrc + EPG);

    const int g = blockIdx.x;
    const int nb = g * NPG;
    const int eb = g * EPG;
    const int tid = threadIdx.x;

    for (int i = tid; i < NPG; i += AT) {
        dsm[i] = dis[nb + i];
        sc[i]  = eoff[nb + i];
    }
    for (int i = tid * 8; i < EPG; i += AT * 8)
        *(uint4*)&bsrc[i] = *(const uint4*)&ebsrc[eb + i];
    for (int i = tid * 4; i < EPG; i += AT * 4)
        *(float4*)&bw[i] = *(const float4*)&ebw[eb + i];
    __syncthreads();

    for (int i = tid * 4; i < NPG * H; i += AT * 4) {
        int node = i >> 6;
        float4 v = *(const float4*)&xw[(size_t)(nb + node) * H + (i & 63)];
        float d = dsm[node];
        v.x *= d; v.y *= d; v.z *= d; v.w *= d;
        *(float4*)&ysm[i] = v;
    }
    __syncthreads();

    const int lane = tid & 31;
    const int warp = tid >> 5;
    const float s0 = gam[lane] * BN_RS,      s1 = gam[lane + 32] * BN_RS;
    const float t0 = bet[lane],              t1 = bet[lane + 32];
    const float bb0 = bias[lane],            bb1 = bias[lane + 32];
    const float p0 = ew_p[lane], p1 = ew_p[lane + 32];
    float pn = p0 * p0 + p1 * p1;
    #pragma unroll
    for (int o = 16; o; o >>= 1) pn += __shfl_xor_sync(0xffffffffu, pn, o);
    const float ipn = rsqrtf(pn);

    for (int dl = warp; dl < NPG; dl += AW) {
        int e0 = dl ? sc[dl - 1] : 0;
        int e1 = sc[dl];
        float a0 = ysm[dl * H + lane];
        float a1 = ysm[dl * H + lane + 32];
        gather_row(bsrc, bw, ysm, e0, e1, lane, a0, a1);
        float d = dsm[dl];
        float v0 = fmaf(d, a0, bb0);
        float v1 = fmaf(d, a1, bb1);
        v0 = fmaxf(fmaf(v0, s0, t0), 0.f);
        v1 = fmaxf(fmaf(v1, s1, t1), 0.f);
        size_t o = (size_t)(nb + dl) * H;
        out[o + lane] = v0;
        out[o + lane + 32] = v1;
        float dsc = v0 * p0 + v1 * p1;
        #pragma unroll
        for (int of = 16; of; of >>= 1) dsc += __shfl_xor_sync(0xffffffffu, dsc, of);
        if (lane == 0) score[nb + dl] = tanhf(dsc * ipn);
    }
}

// ======================================================================
// agg3: fused dis3 + masked CSR + gather + bias/BN/ReLU + mean/max readout
// ======================================================================
constexpr int SMEM_AGG3 = (NPG*H + 2*NPG)*4 + (NPG + 512)*4 + EPG*2 + EPG*4 + 2 * AW * 64 * 4;

__global__ void __launch_bounds__(AT) agg3_kernel(
                            const float* __restrict__ xw,
                            const float* __restrict__ mask,
                            const int* __restrict__ src, const int* __restrict__ dstp,
                            const float* __restrict__ ew,
                            const float* __restrict__ bias, const float* __restrict__ gam,
                            const float* __restrict__ bet, float* __restrict__ emb) {
    extern __shared__ float smf[];
    float* ysm = smf;
    float* dsm = ysm + NPG * H;
    float* msm = dsm + NPG;
    int*   cn  = (int*)(msm + NPG);
    int*   sc  = cn + NPG;
    unsigned short* bsrc = (unsigned short*)(sc + 512);
    float* bw   = (float*)(bsrc + EPG);
    float* psum = bw + EPG;              // [AW][64]
    float* pmax = psum + AW * 64;        // [AW][64]

    const int g = blockIdx.x;
    const int nb = g * NPG;
    const int eb = g * EPG;
    const int tid = threadIdx.x;

    for (int i = tid; i < NPG; i += AT) {
        float m = mask[nb + i];
        msm[i] = m;
        dsm[i] = m;          // degree init = self-loop weight (mask)
        cn[i] = 0;
    }
    __syncthreads();

    // pass 1: masked count + weighted degree
    for (int e = tid; e < EPG; e += AT) {
        int sl = src[eb + e] - nb;
        int dl = dstp[eb + e] - nb;
        if (msm[sl] != 0.f && msm[dl] != 0.f) {
            atomicAdd(&cn[dl], 1);
            atomicAdd(&dsm[dl], ew[eb + e]);
        }
    }
    __syncthreads();
    for (int i = tid; i < NPG; i += AT) {
        float v = dsm[i];
        dsm[i] = (v > 0.f) ? rsqrtf(fmaxf(v, 1e-12f)) : 0.f;
    }
    __syncthreads();

    sc[tid] = (tid < NPG) ? cn[tid] : 0;
    __syncthreads();
    #pragma unroll
    for (int off = 1; off < 512; off <<= 1) {
        int v = sc[tid];
        int a = (tid >= off) ? sc[tid - off] : 0;
        __syncthreads();
        sc[tid] = v + a;
        __syncthreads();
    }
    for (int i = tid; i < NPG; i += AT) cn[i] = 0;
    __syncthreads();
    for (int e = tid; e < EPG; e += AT) {
        int sl = src[eb + e] - nb;
        int dl = dstp[eb + e] - nb;
        if (msm[sl] != 0.f && msm[dl] != 0.f) {
            int pos = (dl ? sc[dl - 1] : 0) + atomicAdd(&cn[dl], 1);
            bsrc[pos] = (unsigned short)sl;
            bw[pos]   = ew[eb + e];
        }
    }

    const int lane = tid & 31;
    const int warp = tid >> 5;
    #pragma unroll
    for (int hf = 0; hf < 2; hf++) {
        __syncthreads();
        for (int i = tid * 4; i < NPG * H; i += AT * 4) {
            int node = i >> 6;
            float4 v = *(const float4*)&xw[(size_t)(nb + node) * H3 + hf * H + (i & 63)];
            float d = dsm[node];
            v.x *= d; v.y *= d; v.z *= d; v.w *= d;
            *(float4*)&ysm[i] = v;
        }
        __syncthreads();
        const int f0 = hf * H + lane, f1 = hf * H + lane + 32;
        const float s0 = gam[f0] * BN_RS, s1 = gam[f1] * BN_RS;
        const float t0 = bet[f0],         t1 = bet[f1];
        const float bb0 = bias[f0],       bb1 = bias[f1];
        float sum0 = 0.f, sum1 = 0.f, mx0 = -INFINITY, mx1 = -INFINITY;
        for (int dl = warp; dl < NPG; dl += AW) {
            if (msm[dl] == 0.f) continue;
            int e0 = dl ? sc[dl - 1] : 0;
            int e1 = sc[dl];
            float a0 = ysm[dl * H + lane];
            float a1 = ysm[dl * H + lane + 32];
            gather_row(bsrc, bw, ysm, e0, e1, lane, a0, a1);
            float d = dsm[dl];
            float v0 = fmaf(d, a0, bb0);
            float v1 = fmaf(d, a1, bb1);
            v0 = fmaxf(fmaf(v0, s0, t0), 0.f);
            v1 = fmaxf(fmaf(v1, s1, t1), 0.f);
            sum0 += v0; sum1 += v1;
            mx0 = fmaxf(mx0, v0); mx1 = fmaxf(mx1, v1);
        }
        psum[warp * 64 + lane]      = sum0;
        psum[warp * 64 + lane + 32] = sum1;
        pmax[warp * 64 + lane]      = mx0;
        pmax[warp * 64 + lane + 32] = mx1;
        __syncthreads();
        if (tid < 64) {   // deterministic fixed-order combine
            float s = 0.f, m = -INFINITY;
            #pragma unroll
            for (int w = 0; w < AW; w++) {
                s += psum[w * 64 + tid];
                m = fmaxf(m, pmax[w * 64 + tid]);
            }
            emb[g * 256 + hf * 64 + tid]       = s * (1.f / KEEP);
            emb[g * 256 + 128 + hf * 64 + tid] = m;
        }
    }
}

// ---------------- top-k (200 of 400) per graph ----------------
__global__ void topk_kernel(const float* __restrict__ score, float* __restrict__ mask,
                            float* __restrict__ gate) {
    __shared__ float s[512];
    __shared__ float orig[NPG];
    __shared__ unsigned char km[NPG];
    __shared__ int cnt;
    const int g = blockIdx.x, tid = threadIdx.x;
    for (int i = tid; i < 512; i += 256) {
        float v = (i < NPG) ? score[g * NPG + i] : -INFINITY;
        s[i] = v;
        if (i < NPG) orig[i] = v;
    }
    if (tid == 0) cnt = 0;
    __syncthreads();
    for (int k = 2; k <= 512; k <<= 1) {
        for (int j = k >> 1; j > 0; j >>= 1) {
            for (int t = tid; t < 512; t += 256) {
                int ixj = t ^ j;
                if (ixj > t) {
                    float a = s[t], b = s[ixj];
                    bool sw = ((t & k) == 0) ? (a > b) : (a < b);
                    if (sw) { s[t] = b; s[ixj] = a; }
                }
            }
            __syncthreads();
        }
    }
    float thr = s[512 - KEEP];
    int local = 0;
    for (int i = tid; i < NPG; i += 256)
        if (orig[i] > thr) local++;
    atomicAdd(&cnt, local);
    __syncthreads();
    if (tid == 0) {
        int rem = KEEP - cnt;
        for (int i = 0; i < NPG; i++) {
            unsigned char m = (orig[i] > thr) ? 1 : 0;
            if (!m && orig[i] == thr && rem > 0) { m = 1; rem--; }
            km[i] = m;
        }
    }
    __syncthreads();
    for (int i = tid; i < NPG; i += 256) {
        float m = km[i] ? 1.f : 0.f;
        mask[g * NPG + i] = m;
        gate[g * NPG + i] = m * orig[i];
    }
}

// ---------------- MLP head ----------------
__global__ void head_kernel(const float* __restrict__ emb,
                            const float* __restrict__ f1w, const float* __restrict__ f1b,
                            const float* __restrict__ gfc, const float* __restrict__ bfc,
                            const float* __restrict__ f2w, const float* __restrict__ f2b,
                            float* __restrict__ out) {
    __shared__ float z[64];
    const int g = blockIdx.x, j = threadIdx.x;
    float acc = f1b[j];
    const float* e = &emb[g * 256];
    #pragma unroll 8
    for (int k = 0; k < 256; k++)
        acc = fmaf(e[k], f1w[k * 64 + j], acc);
    acc = fmaf(acc, gfc[j] * BN_RS, bfc[j]);
    z[j] = fmaxf(acc, 0.f);
    __syncthreads();
    if (j < 2) {
        float o = f2b[j];
        for (int k = 0; k < 64; k++)
            o = fmaf(z[k], f2w[k * 2 + j], o);
        out[g * 2 + j] = o;
    }
}

// ---------------- launch ----------------
extern "C" void kernel_launch(void* const* d_in, const int* in_sizes, int n_in,
                              void* d_out, int out_size) {
    const float* x   = (const float*)d_in[0];
    const int*   ei  = (const int*)  d_in[1];
    const float* ew  = (const float*)d_in[2];
    const float* W1  = (const float*)d_in[4];
    const float* b1  = (const float*)d_in[5];
    const float* g1  = (const float*)d_in[6];
    const float* bt1 = (const float*)d_in[7];
    const float* W2  = (const float*)d_in[8];
    const float* b2  = (const float*)d_in[9];
    const float* g2  = (const float*)d_in[10];
    const float* bt2 = (const float*)d_in[11];
    const float* pp  = (const float*)d_in[12];
    const float* W3  = (const float*)d_in[13];
    const float* b3  = (const float*)d_in[14];
    const float* g3  = (const float*)d_in[15];
    const float* bt3 = (const float*)d_in[16];
    const float* f1w = (const float*)d_in[17];
    const float* f1b = (const float*)d_in[18];
    const float* gfc = (const float*)d_in[19];
    const float* bfc = (const float*)d_in[20];
    const float* f2w = (const float*)d_in[21];
    const float* f2b = (const float*)d_in[22];
    float* out = (float*)d_out;

    const int* src = ei;
    const int* dst = ei + Etot;

    float *p_xw1, *p_h1, *p_xw2, *p_h2, *p_xw3;
    float *p_dis, *p_score, *p_mask, *p_gate, *p_emb, *p_ebw;
    unsigned short* p_ebsrc;
    int* p_eoff;
    __nv_bfloat16 *p_w1h, *p_w1l, *p_w2h, *p_w2l, *p_w3h, *p_w3l;
    cudaGetSymbolAddress((void**)&p_xw1,  g_xw1);
    cudaGetSymbolAddress((void**)&p_h1,   g_h1);
    cudaGetSymbolAddress((void**)&p_xw2,  g_xw2);
    cudaGetSymbolAddress((void**)&p_h2,   g_h2);
    cudaGetSymbolAddress((void**)&p_xw3,  g_xw3);
    cudaGetSymbolAddress((void**)&p_dis,  g_dis);
    cudaGetSymbolAddress((void**)&p_score,g_score);
    cudaGetSymbolAddress((void**)&p_mask, g_mask);
    cudaGetSymbolAddress((void**)&p_gate, g_gate);
    cudaGetSymbolAddress((void**)&p_emb,  g_emb);
    cudaGetSymbolAddress((void**)&p_ebsrc,g_ebsrc);
    cudaGetSymbolAddress((void**)&p_ebw,  g_ebw);
    cudaGetSymbolAddress((void**)&p_eoff, g_eoff);
    cudaGetSymbolAddress((void**)&p_w1h,  g_w1h);
    cudaGetSymbolAddress((void**)&p_w1l,  g_w1l);
    cudaGetSymbolAddress((void**)&p_w2h,  g_w2h);
    cudaGetSymbolAddress((void**)&p_w2l,  g_w2l);
    cudaGetSymbolAddress((void**)&p_w3h,  g_w3h);
    cudaGetSymbolAddress((void**)&p_w3l,  g_w3l);

    constexpr int SM1 = wg_smem(64);
    constexpr int SM3 = wg_smem(128);
    cudaFuncSetAttribute((const void*)wgemm_kernel<64, 400, false>,
                         cudaFuncAttributeMaxDynamicSharedMemorySize, SM1);
    cudaFuncSetAttribute((const void*)wgemm_kernel<64, 64, false>,
                         cudaFuncAttributeMaxDynamicSharedMemorySize, SM1);
    cudaFuncSetAttribute((const void*)wgemm_kernel<128, 64, true>,
                         cudaFuncAttributeMaxDynamicSharedMemorySize, SM3);
    cudaFuncSetAttribute(agg1_kernel, cudaFuncAttributeMaxDynamicSharedMemorySize, SMEM_AGG64);
    cudaFuncSetAttribute(agg2_kernel, cudaFuncAttributeMaxDynamicSharedMemorySize, SMEM_AGG64);
    cudaFuncSetAttribute(agg3_kernel, cudaFuncAttributeMaxDynamicSharedMemorySize, SMEM_AGG3);

    // 0: weight split
    wconv_all_kernel<<<(448*64 + 64*64 + 64*128 + 255) / 256, 256>>>(
        W1, W2, W3, p_w1h, p_w1l, p_w2h, p_w2l, p_w3h, p_w3l);

    // 1: GCN1 GEMM
    wgemm_kernel<64, 400, false><<<Ntot / 128, 256, SM1>>>(x, p_w1h, p_w1l, nullptr, p_xw1);
    // 2: GCN1 aggregation (fused degree + CSR build/persist)
    agg1_kernel<<<Bg, AT, SMEM_AGG64>>>(p_xw1, src, dst, ew, b1, g1, bt1, p_h1,
                                        p_dis, p_ebsrc, p_ebw, p_eoff);
    // 3: GCN2 GEMM
    wgemm_kernel<64, 64, false><<<Ntot / 128, 256, SM1>>>(p_h1, p_w2h, p_w2l, nullptr, p_xw2);
    // 4: GCN2 aggregation (reused CSR, fused score)
    agg2_kernel<<<Bg, AT, SMEM_AGG64>>>(p_xw2, p_dis, p_ebsrc, p_ebw, p_eoff, pp,
                                        b2, g2, bt2, p_h2, p_score);
    // 5: TopK
    topk_kernel<<<Bg, 256>>>(p_score, p_mask, p_gate);
    // 6: GCN3 GEMM (rows gated by score*mask)
    wgemm_kernel<128, 64, true><<<Ntot / 128, 256, SM3>>>(p_h2, p_w3h, p_w3l, p_gate, p_xw3);
    // 7: GCN3 aggregation (fused dis3 + masked CSR + readout)
    agg3_kernel<<<Bg, AT, SMEM_AGG3>>>(p_xw3, p_mask, src, dst, ew, b3, g3, bt3, p_emb);
    // 8: head
    head_kernel<<<Bg, 64>>>(p_emb, f1w, f1b, gfc, bfc, f2w, f2b, out);
}